// round 7
// baseline (speedup 1.0000x reference)
#include <cuda_runtime.h>
#include <cuda_bf16.h>
#include <cstdint>

// ---------------- problem constants ----------------
constexpr int Bc = 4, Tc = 4096, Cc = 120, Hc = 64;
constexpr float SCALE = 0.09128709291752768f;  // 1/sqrt(C)
constexpr int KTILE = 64;
constexpr int NKT = Tc / KTILE;  // 64 key tiles
constexpr int LDK = 72;          // padded smem row stride (elements) = 144 B
constexpr int ABUF = KTILE * LDK * 2;      // 9216 B per array
constexpr int TILEBUF = 4 * ABUF;          // 36864 B per stage

// ---------------- device scratch (allocation-free rule) ----------------
__device__ __align__(16) __nv_bfloat16 g_qh[Bc * Tc * Hc];
__device__ __align__(16) __nv_bfloat16 g_ql[Bc * Tc * Hc];
__device__ __align__(16) __nv_bfloat16 g_kh[Bc * Tc * Hc];
__device__ __align__(16) __nv_bfloat16 g_kl[Bc * Tc * Hc];
// V transposed: [b][h][t]
__device__ __align__(16) __nv_bfloat16 g_vth[Bc * Hc * Tc];
__device__ __align__(16) __nv_bfloat16 g_vtl[Bc * Hc * Tc];

// ---------------- PTX helpers (baseline sm_80+/sm_103 features) ----------------
__device__ __forceinline__ void mma16816(float* d, const uint32_t* a,
                                         uint32_t b0, uint32_t b1) {
    asm volatile(
        "mma.sync.aligned.m16n8k16.row.col.f32.bf16.bf16.f32 "
        "{%0,%1,%2,%3}, {%4,%5,%6,%7}, {%8,%9}, {%0,%1,%2,%3};"
        : "+f"(d[0]), "+f"(d[1]), "+f"(d[2]), "+f"(d[3])
        : "r"(a[0]), "r"(a[1]), "r"(a[2]), "r"(a[3]), "r"(b0), "r"(b1));
}
__device__ __forceinline__ void ldsm2(uint32_t& r0, uint32_t& r1, uint32_t addr) {
    asm volatile("ldmatrix.sync.aligned.m8n8.x2.shared.b16 {%0,%1}, [%2];"
                 : "=r"(r0), "=r"(r1) : "r"(addr));
}
__device__ __forceinline__ uint32_t smem_u32(const void* p) {
    uint32_t a;
    asm("{ .reg .u64 t; cvta.to.shared.u64 t, %1; cvt.u32.u64 %0, t; }"
        : "=r"(a) : "l"(p));
    return a;
}
__device__ __forceinline__ void cpasync16(uint32_t dst, const void* src) {
    asm volatile("cp.async.ca.shared.global [%0], [%1], 16;" :: "r"(dst), "l"(src));
}
#define CP_COMMIT() asm volatile("cp.async.commit_group;" ::: "memory")
#define CP_WAIT0()  asm volatile("cp.async.wait_group 0;" ::: "memory")

__device__ __forceinline__ uint32_t pk(float hi, float lo) {
    uint32_t r;
    asm("cvt.rn.bf16x2.f32 %0, %1, %2;" : "=r"(r) : "f"(hi), "f"(lo));
    return r;
}
__device__ __forceinline__ float bf_round(float x) {
    return __bfloat162float(__float2bfloat16(x));
}
__device__ __forceinline__ unsigned long long ffma2(unsigned long long a,
                                                    unsigned long long b,
                                                    unsigned long long c) {
    unsigned long long d;
    asm("fma.rn.f32x2 %0, %1, %2, %3;" : "=l"(d) : "l"(a), "l"(b), "l"(c));
    return d;
}
__device__ __forceinline__ float2 u2f(unsigned long long u) {
    float2 r;
    asm("mov.b64 {%0, %1}, %2;" : "=f"(r.x), "=f"(r.y) : "l"(u));
    return r;
}
__device__ __forceinline__ unsigned long long pk64(float lo, float hi) {
    unsigned long long r;
    asm("mov.b64 %0, {%1, %2};" : "=l"(r) : "f"(lo), "f"(hi));
    return r;
}

// ---------------- Kernel 1: QKV projection ----------------
// 512 CTAs x 192 threads; 32 rows/CTA; thread = (matrix m, column h).
// W loaded with COALESCED float4 (fixes R6 scalar-LDG bottleneck), read from
// smem native [c][h] (bank = h mod 32, conflict-free). x broadcast LDS.128.
constexpr int PROJ_SMEM = (3 * Cc * Hc + 32 * Cc) * 4;  // 107,520 B
__global__ void __launch_bounds__(192)
proj_kernel(const float* __restrict__ x,
            const float* __restrict__ Wk,
            const float* __restrict__ Wq,
            const float* __restrict__ Wv) {
    extern __shared__ float ps[];
    float* sW = ps;                 // [3][120][64]
    float* xs = ps + 3 * Cc * Hc;   // [32][120]

    const int tid = threadIdx.x;
    {
        const float4* s0 = reinterpret_cast<const float4*>(Wk);
        const float4* s1 = reinterpret_cast<const float4*>(Wq);
        const float4* s2 = reinterpret_cast<const float4*>(Wv);
        float4* d0 = reinterpret_cast<float4*>(sW);
        float4* d1 = reinterpret_cast<float4*>(sW + Cc * Hc);
        float4* d2 = reinterpret_cast<float4*>(sW + 2 * Cc * Hc);
#pragma unroll
        for (int j = tid; j < Cc * Hc / 4; j += 192) {
            d0[j] = s0[j];
            d1[j] = s1[j];
            d2[j] = s2[j];
        }
    }
    const int row0 = blockIdx.x * 32;
    {
        const float4* xg = reinterpret_cast<const float4*>(x + (long long)row0 * Cc);
        float4* xs4 = reinterpret_cast<float4*>(xs);
#pragma unroll
        for (int i = 0; i < 5; i++) xs4[tid + i * 192] = xg[tid + i * 192];
    }
    __syncthreads();

    const int m = tid >> 6, h = tid & 63;
    const float* wcol = sW + m * Cc * Hc + h;

    unsigned long long acc[32];
#pragma unroll
    for (int r = 0; r < 32; r++) acc[r] = 0ull;

#pragma unroll 1
    for (int c8 = 0; c8 < 15; c8++) {
        float wv[8];
#pragma unroll
        for (int i = 0; i < 8; i++) wv[i] = wcol[(c8 * 8 + i) * Hc];
        const unsigned long long w0 = pk64(wv[0], wv[1]);
        const unsigned long long w1 = pk64(wv[2], wv[3]);
        const unsigned long long w2 = pk64(wv[4], wv[5]);
        const unsigned long long w3 = pk64(wv[6], wv[7]);
#pragma unroll
        for (int r = 0; r < 32; r++) {
            const ulonglong2 x01 = *reinterpret_cast<const ulonglong2*>(&xs[r * Cc + c8 * 8]);
            const ulonglong2 x23 = *reinterpret_cast<const ulonglong2*>(&xs[r * Cc + c8 * 8 + 4]);
            acc[r] = ffma2(x01.x, w0, acc[r]);
            acc[r] = ffma2(x01.y, w1, acc[r]);
            acc[r] = ffma2(x23.x, w2, acc[r]);
            acc[r] = ffma2(x23.y, w3, acc[r]);
        }
    }

#pragma unroll
    for (int r = 0; r < 32; r++) {
        const float2 f = u2f(acc[r]);
        float s = f.x + f.y;
        const int row = row0 + r;
        if (m == 1) {  // Q (with scale)
            s *= SCALE;
            const __nv_bfloat16 hi = __float2bfloat16(s);
            g_qh[row * Hc + h] = hi;
            g_ql[row * Hc + h] = __float2bfloat16(s - __bfloat162float(hi));
        } else if (m == 0) {  // K
            const __nv_bfloat16 hi = __float2bfloat16(s);
            g_kh[row * Hc + h] = hi;
            g_kl[row * Hc + h] = __float2bfloat16(s - __bfloat162float(hi));
        } else {  // V transposed
            const int b = row >> 12, t = row & 4095;
            const int vidx = (b * Hc + h) * Tc + t;
            const __nv_bfloat16 hi = __float2bfloat16(s);
            g_vth[vidx] = hi;
            g_vtl[vidx] = __float2bfloat16(s - __bfloat162float(hi));
        }
    }
}

// ---------------- Kernel 2: HMMA flash attention ----------------
// 128 CTAs x 256 thr; 16 q/warp; 64 key tiles; 16-key chunks; cp.async double
// buffer; QK uses per-term accumulators (6 chains of depth 4) to break the
// RAW chain that capped tensor util at 59.5%.
__global__ void __launch_bounds__(256, 1)
attn_kernel(float* __restrict__ out) {
    extern __shared__ char dsm[];  // 2 x TILEBUF

    const int tid = threadIdx.x;
    const int w = tid >> 5;
    const int lane = tid & 31;
    const int g = lane >> 2;
    const int tig = lane & 3;
    const int b = blockIdx.y;
    const long long qrow = (long long)b * Tc + blockIdx.x * 128 + 16 * w + g;

    // ---- Q fragments in registers ----
    uint32_t qh[4][4], ql[4][4];
#pragma unroll
    for (int s = 0; s < 4; s++) {
        const int d0 = 16 * s + 2 * tig;
        qh[s][0] = *(const uint32_t*)&g_qh[qrow * Hc + d0];
        qh[s][1] = *(const uint32_t*)&g_qh[(qrow + 8) * Hc + d0];
        qh[s][2] = *(const uint32_t*)&g_qh[qrow * Hc + d0 + 8];
        qh[s][3] = *(const uint32_t*)&g_qh[(qrow + 8) * Hc + d0 + 8];
        ql[s][0] = *(const uint32_t*)&g_ql[qrow * Hc + d0];
        ql[s][1] = *(const uint32_t*)&g_ql[(qrow + 8) * Hc + d0];
        ql[s][2] = *(const uint32_t*)&g_ql[qrow * Hc + d0 + 8];
        ql[s][3] = *(const uint32_t*)&g_ql[(qrow + 8) * Hc + d0 + 8];
    }

    float O[8][4];
#pragma unroll
    for (int j = 0; j < 8; j++)
#pragma unroll
        for (int i = 0; i < 4; i++) O[j][i] = 0.f;
    float rl = 0.f, rh = 0.f;

    const uint32_t sb = smem_u32(dsm);
    const uint32_t laneoff = (uint32_t)((lane & 7) * (LDK * 2) + ((lane >> 3) & 1) * 16);

    auto prefetch = [&](int kt, int p) {
        const uint32_t bb = sb + p * TILEBUF;
        const long long kb = (long long)b * Tc + kt * KTILE;
        const long long vb = (long long)b * Hc * Tc + kt * KTILE;
#pragma unroll
        for (int it = 0; it < 8; it++) {
            const int rc = (it & 1) * 256 + tid;
            const int row = rc >> 3, h8 = rc & 7;
            const uint32_t doff = (uint32_t)(row * (LDK * 2) + h8 * 16);
            if (it < 2)
                cpasync16(bb + doff, g_kh + (kb + row) * Hc + h8 * 8);
            else if (it < 4)
                cpasync16(bb + ABUF + doff, g_kl + (kb + row) * Hc + h8 * 8);
            else if (it < 6)
                cpasync16(bb + 2 * ABUF + doff, g_vth + vb + (long long)row * Tc + h8 * 8);
            else
                cpasync16(bb + 3 * ABUF + doff, g_vtl + vb + (long long)row * Tc + h8 * 8);
        }
    };

    prefetch(0, 0);
    CP_COMMIT();

    for (int kt = 0; kt < NKT; kt++) {
        CP_WAIT0();
        __syncthreads();
        if (kt + 1 < NKT) {
            prefetch(kt + 1, (kt + 1) & 1);
            CP_COMMIT();
        }

        const uint32_t bb = sb + (kt & 1) * TILEBUF;
        const uint32_t aKh = bb + laneoff;
        const uint32_t aKl = bb + ABUF + laneoff;
        const uint32_t aVh = bb + 2 * ABUF + laneoff;
        const uint32_t aVl = bb + 3 * ABUF + laneoff;

#pragma unroll
        for (int s = 0; s < 4; s++) {  // 16-key chunks
            // per-term accumulators: 6 independent MMA chains of depth 4
            float Sa0[4] = {0.f, 0.f, 0.f, 0.f}, Sb0[4] = {0.f, 0.f, 0.f, 0.f};
            float Sc0[4] = {0.f, 0.f, 0.f, 0.f};
            float Sa1[4] = {0.f, 0.f, 0.f, 0.f}, Sb1[4] = {0.f, 0.f, 0.f, 0.f};
            float Sc1[4] = {0.f, 0.f, 0.f, 0.f};
            const uint32_t jo0 = (uint32_t)(2 * s) * (8 * LDK * 2);
            const uint32_t jo1 = jo0 + 8 * LDK * 2;

#pragma unroll
            for (int sd = 0; sd < 4; sd++) {
                uint32_t h0, h1, l0, l1;
                ldsm2(h0, h1, aKh + jo0 + sd * 32);
                ldsm2(l0, l1, aKl + jo0 + sd * 32);
                mma16816(Sa0, qh[sd], h0, h1);
                mma16816(Sb0, ql[sd], h0, h1);
                mma16816(Sc0, qh[sd], l0, l1);
                ldsm2(h0, h1, aKh + jo1 + sd * 32);
                ldsm2(l0, l1, aKl + jo1 + sd * 32);
                mma16816(Sa1, qh[sd], h0, h1);
                mma16816(Sb1, ql[sd], h0, h1);
                mma16816(Sc1, qh[sd], l0, l1);
            }

            float S0[4], S1[4];
#pragma unroll
            for (int i = 0; i < 4; i++) {
                S0[i] = (Sa0[i] + Sb0[i]) + Sc0[i];
                S1[i] = (Sa1[i] + Sb1[i]) + Sc1[i];
            }

            // ---- exp + repack into P A-fragments ----
            const float e0 = __expf(S0[0]), e1 = __expf(S0[1]);
            const float e2 = __expf(S0[2]), e3 = __expf(S0[3]);
            const float f0 = __expf(S1[0]), f1 = __expf(S1[1]);
            const float f2 = __expf(S1[2]), f3 = __expf(S1[3]);
            rl += (e0 + e1) + (f0 + f1);
            rh += (e2 + e3) + (f2 + f3);
            uint32_t ph[4], pl[4];
            ph[0] = pk(e1, e0);
            ph[1] = pk(e3, e2);
            ph[2] = pk(f1, f0);
            ph[3] = pk(f3, f2);
            pl[0] = pk(e1 - bf_round(e1), e0 - bf_round(e0));
            pl[1] = pk(e3 - bf_round(e3), e2 - bf_round(e2));
            pl[2] = pk(f1 - bf_round(f1), f0 - bf_round(f0));
            pl[3] = pk(f3 - bf_round(f3), f2 - bf_round(f2));

            // ---- PV for this chunk (8-way ILP over jd) ----
#pragma unroll
            for (int jd = 0; jd < 8; jd++) {
                const uint32_t vo = (uint32_t)jd * (8 * LDK * 2) + (uint32_t)s * 32;
                uint32_t b0, b1, c0, c1;
                ldsm2(b0, b1, aVh + vo);
                mma16816(O[jd], ph, b0, b1);
                mma16816(O[jd], pl, b0, b1);
                ldsm2(c0, c1, aVl + vo);
                mma16816(O[jd], ph, c0, c1);
            }
        }
    }

    // ---- row sums, normalize, store ----
    rl += __shfl_xor_sync(0xffffffffu, rl, 1);
    rl += __shfl_xor_sync(0xffffffffu, rl, 2);
    rh += __shfl_xor_sync(0xffffffffu, rh, 1);
    rh += __shfl_xor_sync(0xffffffffu, rh, 2);
    const float il = 1.0f / rl;
    const float ih = 1.0f / rh;

#pragma unroll
    for (int j = 0; j < 8; j++) {
        const int d0 = 8 * j + 2 * tig;
        float2 v0 = make_float2(O[j][0] * il, O[j][1] * il);
        *(float2*)&out[qrow * Hc + d0] = v0;
        float2 v1 = make_float2(O[j][2] * ih, O[j][3] * ih);
        *(float2*)&out[(qrow + 8) * Hc + d0] = v1;
    }
}

extern "C" void kernel_launch(void* const* d_in, const int* in_sizes, int n_in,
                              void* d_out, int out_size) {
    // x is the unique large tensor; weights keep relative order Wk, Wq, Wv.
    const float* x = nullptr;
    const float* w[3] = {nullptr, nullptr, nullptr};
    int wn = 0;
    for (int i = 0; i < n_in; i++) {
        if (in_sizes[i] == Bc * Tc * Cc) x = (const float*)d_in[i];
        else if (wn < 3) w[wn++] = (const float*)d_in[i];
    }

    static bool configured = false;
    if (!configured) {
        cudaFuncSetAttribute(proj_kernel, cudaFuncAttributeMaxDynamicSharedMemorySize,
                             PROJ_SMEM);
        cudaFuncSetAttribute(attn_kernel, cudaFuncAttributeMaxDynamicSharedMemorySize,
                             2 * TILEBUF);
        configured = true;
    }

    proj_kernel<<<512, 192, PROJ_SMEM>>>(x, w[0], w[1], w[2]);

    dim3 grid(Tc / 128, Bc);
    attn_kernel<<<grid, 256, 2 * TILEBUF>>>((float*)d_out);
}

// round 8
// speedup vs baseline: 1.0738x; 1.0738x over previous
#include <cuda_runtime.h>
#include <cuda_bf16.h>
#include <cstdint>

// ---------------- problem constants ----------------
constexpr int Bc = 4, Tc = 4096, Cc = 120, Hc = 64;
constexpr float SCALE = 0.09128709291752768f;  // 1/sqrt(C)
constexpr int KTILE = 64;
constexpr int NKT = Tc / KTILE;  // 64 key tiles
constexpr int LDK = 72;          // padded smem row stride (elements) = 144 B
constexpr int ABUF = KTILE * LDK * 2;      // 9216 B per array
constexpr int TILEBUF = 4 * ABUF;          // 36864 B per stage

// ---------------- device scratch (allocation-free rule) ----------------
__device__ __align__(16) __nv_bfloat16 g_qh[Bc * Tc * Hc];
__device__ __align__(16) __nv_bfloat16 g_ql[Bc * Tc * Hc];
__device__ __align__(16) __nv_bfloat16 g_kh[Bc * Tc * Hc];
__device__ __align__(16) __nv_bfloat16 g_kl[Bc * Tc * Hc];
// V transposed: [b][h][t]
__device__ __align__(16) __nv_bfloat16 g_vth[Bc * Hc * Tc];
__device__ __align__(16) __nv_bfloat16 g_vtl[Bc * Hc * Tc];

// ---------------- PTX helpers (baseline sm_80+/sm_103 features) ----------------
__device__ __forceinline__ void mma16816(float* d, const uint32_t* a,
                                         uint32_t b0, uint32_t b1) {
    asm volatile(
        "mma.sync.aligned.m16n8k16.row.col.f32.bf16.bf16.f32 "
        "{%0,%1,%2,%3}, {%4,%5,%6,%7}, {%8,%9}, {%0,%1,%2,%3};"
        : "+f"(d[0]), "+f"(d[1]), "+f"(d[2]), "+f"(d[3])
        : "r"(a[0]), "r"(a[1]), "r"(a[2]), "r"(a[3]), "r"(b0), "r"(b1));
}
__device__ __forceinline__ void ldsm2(uint32_t& r0, uint32_t& r1, uint32_t addr) {
    asm volatile("ldmatrix.sync.aligned.m8n8.x2.shared.b16 {%0,%1}, [%2];"
                 : "=r"(r0), "=r"(r1) : "r"(addr));
}
__device__ __forceinline__ uint32_t smem_u32(const void* p) {
    uint32_t a;
    asm("{ .reg .u64 t; cvta.to.shared.u64 t, %1; cvt.u32.u64 %0, t; }"
        : "=r"(a) : "l"(p));
    return a;
}
__device__ __forceinline__ void cpasync16(uint32_t dst, const void* src) {
    asm volatile("cp.async.ca.shared.global [%0], [%1], 16;" :: "r"(dst), "l"(src));
}
#define CP_COMMIT() asm volatile("cp.async.commit_group;" ::: "memory")
#define CP_WAIT0()  asm volatile("cp.async.wait_group 0;" ::: "memory")

__device__ __forceinline__ uint32_t pk(float hi, float lo) {
    uint32_t r;
    asm("cvt.rn.bf16x2.f32 %0, %1, %2;" : "=r"(r) : "f"(hi), "f"(lo));
    return r;
}
__device__ __forceinline__ unsigned long long ffma2(unsigned long long a,
                                                    unsigned long long b,
                                                    unsigned long long c) {
    unsigned long long d;
    asm("fma.rn.f32x2 %0, %1, %2, %3;" : "=l"(d) : "l"(a), "l"(b), "l"(c));
    return d;
}
__device__ __forceinline__ float2 u2f(unsigned long long u) {
    float2 r;
    asm("mov.b64 {%0, %1}, %2;" : "=f"(r.x), "=f"(r.y) : "l"(u));
    return r;
}
__device__ __forceinline__ unsigned long long pk64(float lo, float hi) {
    unsigned long long r;
    asm("mov.b64 %0, {%1, %2};" : "=l"(r) : "f"(lo), "f"(hi));
    return r;
}

// ---------------- Kernel 1: QKV projection ----------------
constexpr int PROJ_SMEM = (3 * Cc * Hc + 32 * Cc) * 4;  // 107,520 B
__global__ void __launch_bounds__(192)
proj_kernel(const float* __restrict__ x,
            const float* __restrict__ Wk,
            const float* __restrict__ Wq,
            const float* __restrict__ Wv) {
    extern __shared__ float ps[];
    float* sW = ps;                 // [3][120][64]
    float* xs = ps + 3 * Cc * Hc;   // [32][120]

    const int tid = threadIdx.x;
    {
        const float4* s0 = reinterpret_cast<const float4*>(Wk);
        const float4* s1 = reinterpret_cast<const float4*>(Wq);
        const float4* s2 = reinterpret_cast<const float4*>(Wv);
        float4* d0 = reinterpret_cast<float4*>(sW);
        float4* d1 = reinterpret_cast<float4*>(sW + Cc * Hc);
        float4* d2 = reinterpret_cast<float4*>(sW + 2 * Cc * Hc);
#pragma unroll
        for (int j = tid; j < Cc * Hc / 4; j += 192) {
            d0[j] = s0[j];
            d1[j] = s1[j];
            d2[j] = s2[j];
        }
    }
    const int row0 = blockIdx.x * 32;
    {
        const float4* xg = reinterpret_cast<const float4*>(x + (long long)row0 * Cc);
        float4* xs4 = reinterpret_cast<float4*>(xs);
#pragma unroll
        for (int i = 0; i < 5; i++) xs4[tid + i * 192] = xg[tid + i * 192];
    }
    __syncthreads();

    const int m = tid >> 6, h = tid & 63;
    const float* wcol = sW + m * Cc * Hc + h;

    unsigned long long acc[32];
#pragma unroll
    for (int r = 0; r < 32; r++) acc[r] = 0ull;

#pragma unroll 1
    for (int c8 = 0; c8 < 15; c8++) {
        float wv[8];
#pragma unroll
        for (int i = 0; i < 8; i++) wv[i] = wcol[(c8 * 8 + i) * Hc];
        const unsigned long long w0 = pk64(wv[0], wv[1]);
        const unsigned long long w1 = pk64(wv[2], wv[3]);
        const unsigned long long w2 = pk64(wv[4], wv[5]);
        const unsigned long long w3 = pk64(wv[6], wv[7]);
#pragma unroll
        for (int r = 0; r < 32; r++) {
            const ulonglong2 x01 = *reinterpret_cast<const ulonglong2*>(&xs[r * Cc + c8 * 8]);
            const ulonglong2 x23 = *reinterpret_cast<const ulonglong2*>(&xs[r * Cc + c8 * 8 + 4]);
            acc[r] = ffma2(x01.x, w0, acc[r]);
            acc[r] = ffma2(x01.y, w1, acc[r]);
            acc[r] = ffma2(x23.x, w2, acc[r]);
            acc[r] = ffma2(x23.y, w3, acc[r]);
        }
    }

#pragma unroll
    for (int r = 0; r < 32; r++) {
        const float2 f = u2f(acc[r]);
        float s = f.x + f.y;
        const int row = row0 + r;
        if (m == 1) {  // Q (with scale)
            s *= SCALE;
            const __nv_bfloat16 hi = __float2bfloat16(s);
            g_qh[row * Hc + h] = hi;
            g_ql[row * Hc + h] = __float2bfloat16(s - __bfloat162float(hi));
        } else if (m == 0) {  // K
            const __nv_bfloat16 hi = __float2bfloat16(s);
            g_kh[row * Hc + h] = hi;
            g_kl[row * Hc + h] = __float2bfloat16(s - __bfloat162float(hi));
        } else {  // V transposed
            const int b = row >> 12, t = row & 4095;
            const int vidx = (b * Hc + h) * Tc + t;
            const __nv_bfloat16 hi = __float2bfloat16(s);
            g_vth[vidx] = hi;
            g_vtl[vidx] = __float2bfloat16(s - __bfloat162float(hi));
        }
    }
}

// ---------------- Kernel 2: HMMA flash attention ----------------
// 128 CTAs x 256 thr; 16 q/warp; 64 key tiles; 16-key chunks; cp.async double
// buffer. Software-pipelined: QK(s+1) is issued BEFORE exp(s) so the tensor
// pipe stays fed while the warp computes exp on the FMA/MUFU pipes.
__global__ void __launch_bounds__(256, 1)
attn_kernel(float* __restrict__ out) {
    extern __shared__ char dsm[];  // 2 x TILEBUF

    const int tid = threadIdx.x;
    const int w = tid >> 5;
    const int lane = tid & 31;
    const int g = lane >> 2;
    const int tig = lane & 3;
    const int b = blockIdx.y;
    const long long qrow = (long long)b * Tc + blockIdx.x * 128 + 16 * w + g;

    // ---- Q fragments in registers ----
    uint32_t qh[4][4], ql[4][4];
#pragma unroll
    for (int s = 0; s < 4; s++) {
        const int d0 = 16 * s + 2 * tig;
        qh[s][0] = *(const uint32_t*)&g_qh[qrow * Hc + d0];
        qh[s][1] = *(const uint32_t*)&g_qh[(qrow + 8) * Hc + d0];
        qh[s][2] = *(const uint32_t*)&g_qh[qrow * Hc + d0 + 8];
        qh[s][3] = *(const uint32_t*)&g_qh[(qrow + 8) * Hc + d0 + 8];
        ql[s][0] = *(const uint32_t*)&g_ql[qrow * Hc + d0];
        ql[s][1] = *(const uint32_t*)&g_ql[(qrow + 8) * Hc + d0];
        ql[s][2] = *(const uint32_t*)&g_ql[qrow * Hc + d0 + 8];
        ql[s][3] = *(const uint32_t*)&g_ql[(qrow + 8) * Hc + d0 + 8];
    }

    float O[8][4];
#pragma unroll
    for (int j = 0; j < 8; j++)
#pragma unroll
        for (int i = 0; i < 4; i++) O[j][i] = 0.f;
    float rl = 0.f, rh = 0.f;

    const uint32_t sb = smem_u32(dsm);
    const uint32_t laneoff = (uint32_t)((lane & 7) * (LDK * 2) + ((lane >> 3) & 1) * 16);

    auto prefetch = [&](int kt, int p) {
        const uint32_t bb = sb + p * TILEBUF;
        const long long kb = (long long)b * Tc + kt * KTILE;
        const long long vb = (long long)b * Hc * Tc + kt * KTILE;
#pragma unroll
        for (int it = 0; it < 8; it++) {
            const int rc = (it & 1) * 256 + tid;
            const int row = rc >> 3, h8 = rc & 7;
            const uint32_t doff = (uint32_t)(row * (LDK * 2) + h8 * 16);
            if (it < 2)
                cpasync16(bb + doff, g_kh + (kb + row) * Hc + h8 * 8);
            else if (it < 4)
                cpasync16(bb + ABUF + doff, g_kl + (kb + row) * Hc + h8 * 8);
            else if (it < 6)
                cpasync16(bb + 2 * ABUF + doff, g_vth + vb + (long long)row * Tc + h8 * 8);
            else
                cpasync16(bb + 3 * ABUF + doff, g_vtl + vb + (long long)row * Tc + h8 * 8);
        }
    };

    prefetch(0, 0);
    CP_COMMIT();

    float S[2][2][4];  // ping-pong S buffers (chunk parity, n-tile, frag)

    for (int kt = 0; kt < NKT; kt++) {
        CP_WAIT0();
        __syncthreads();
        if (kt + 1 < NKT) {
            prefetch(kt + 1, (kt + 1) & 1);
            CP_COMMIT();
        }

        const uint32_t bb = sb + (kt & 1) * TILEBUF;
        const uint32_t aKh = bb + laneoff;
        const uint32_t aKl = bb + ABUF + laneoff;
        const uint32_t aVh = bb + 2 * ABUF + laneoff;
        const uint32_t aVl = bb + 3 * ABUF + laneoff;

        // QK of a 16-key chunk (3-term split bf16) into S[p]
        auto qk_chunk = [&](int s, int p) {
            float* S0 = S[p][0];
            float* S1 = S[p][1];
#pragma unroll
            for (int i = 0; i < 4; i++) { S0[i] = 0.f; S1[i] = 0.f; }
            const uint32_t jo0 = (uint32_t)(2 * s) * (8 * LDK * 2);
            const uint32_t jo1 = jo0 + 8 * LDK * 2;
#pragma unroll
            for (int sd = 0; sd < 4; sd++) {
                uint32_t b0, b1, c0, c1;
                ldsm2(b0, b1, aKh + jo0 + sd * 32);
                mma16816(S0, qh[sd], b0, b1);
                mma16816(S0, ql[sd], b0, b1);
                ldsm2(c0, c1, aKl + jo0 + sd * 32);
                mma16816(S0, qh[sd], c0, c1);
                ldsm2(b0, b1, aKh + jo1 + sd * 32);
                mma16816(S1, qh[sd], b0, b1);
                mma16816(S1, ql[sd], b0, b1);
                ldsm2(c0, c1, aKl + jo1 + sd * 32);
                mma16816(S1, qh[sd], c0, c1);
            }
        };

        qk_chunk(0, 0);

#pragma unroll
        for (int s = 0; s < 4; s++) {
            // issue next chunk's QK first: tensor pipe stays busy during exp
            if (s < 3) qk_chunk(s + 1, (s + 1) & 1);

            const float* S0 = S[s & 1][0];
            const float* S1 = S[s & 1][1];

            // ---- exp + repack into P A-fragments ----
            const float e0 = __expf(S0[0]), e1 = __expf(S0[1]);
            const float e2 = __expf(S0[2]), e3 = __expf(S0[3]);
            const float f0 = __expf(S1[0]), f1 = __expf(S1[1]);
            const float f2 = __expf(S1[2]), f3 = __expf(S1[3]);
            rl += (e0 + e1) + (f0 + f1);
            rh += (e2 + e3) + (f2 + f3);
            uint32_t ph[4], pl[4];
            ph[0] = pk(e1, e0);
            ph[1] = pk(e3, e2);
            ph[2] = pk(f1, f0);
            ph[3] = pk(f3, f2);
            // rounded values recovered by bit ops from the packed bf16x2
#pragma unroll
            for (int i = 0; i < 4; i++) {
                const float lo = (i == 0) ? e0 : (i == 1) ? e2 : (i == 2) ? f0 : f2;
                const float hi = (i == 0) ? e1 : (i == 1) ? e3 : (i == 2) ? f1 : f3;
                const float rlo = __uint_as_float(ph[i] << 16);
                const float rhi = __uint_as_float(ph[i] & 0xffff0000u);
                pl[i] = pk(hi - rhi, lo - rlo);
            }

            // ---- PV for this chunk (8-way ILP over jd) ----
#pragma unroll
            for (int jd = 0; jd < 8; jd++) {
                const uint32_t vo = (uint32_t)jd * (8 * LDK * 2) + (uint32_t)s * 32;
                uint32_t b0, b1, c0, c1;
                ldsm2(b0, b1, aVh + vo);
                mma16816(O[jd], ph, b0, b1);
                mma16816(O[jd], pl, b0, b1);
                ldsm2(c0, c1, aVl + vo);
                mma16816(O[jd], ph, c0, c1);
            }
        }
    }

    // ---- row sums, normalize, store ----
    rl += __shfl_xor_sync(0xffffffffu, rl, 1);
    rl += __shfl_xor_sync(0xffffffffu, rl, 2);
    rh += __shfl_xor_sync(0xffffffffu, rh, 1);
    rh += __shfl_xor_sync(0xffffffffu, rh, 2);
    const float il = 1.0f / rl;
    const float ih = 1.0f / rh;

#pragma unroll
    for (int j = 0; j < 8; j++) {
        const int d0 = 8 * j + 2 * tig;
        float2 v0 = make_float2(O[j][0] * il, O[j][1] * il);
        *(float2*)&out[qrow * Hc + d0] = v0;
        float2 v1 = make_float2(O[j][2] * ih, O[j][3] * ih);
        *(float2*)&out[(qrow + 8) * Hc + d0] = v1;
    }
}

extern "C" void kernel_launch(void* const* d_in, const int* in_sizes, int n_in,
                              void* d_out, int out_size) {
    // x is the unique large tensor; weights keep relative order Wk, Wq, Wv.
    const float* x = nullptr;
    const float* w[3] = {nullptr, nullptr, nullptr};
    int wn = 0;
    for (int i = 0; i < n_in; i++) {
        if (in_sizes[i] == Bc * Tc * Cc) x = (const float*)d_in[i];
        else if (wn < 3) w[wn++] = (const float*)d_in[i];
    }

    static bool configured = false;
    if (!configured) {
        cudaFuncSetAttribute(proj_kernel, cudaFuncAttributeMaxDynamicSharedMemorySize,
                             PROJ_SMEM);
        cudaFuncSetAttribute(attn_kernel, cudaFuncAttributeMaxDynamicSharedMemorySize,
                             2 * TILEBUF);
        configured = true;
    }

    proj_kernel<<<512, 192, PROJ_SMEM>>>(x, w[0], w[1], w[2]);

    dim3 grid(Tc / 128, Bc);
    attn_kernel<<<grid, 256, 2 * TILEBUF>>>((float*)d_out);
}

// round 9
// speedup vs baseline: 1.2589x; 1.1724x over previous
#include <cuda_runtime.h>
#include <cuda_bf16.h>
#include <cstdint>

// ---------------- problem constants ----------------
constexpr int Bc = 4, Tc = 4096, Cc = 120, Hc = 64;
constexpr float SCALE = 0.09128709291752768f;  // 1/sqrt(C)
constexpr int KTILE = 64;
constexpr int NKT = Tc / KTILE;   // 64 key tiles
constexpr int RSTRIDE = 272;      // smem row stride bytes (68 f32, conflict-free)
constexpr int VOFF = 64 * RSTRIDE;        // 17408: V region offset in stage
constexpr int STAGE = 2 * 64 * RSTRIDE;   // 34816 bytes per stage (K + V)

// ---------------- device scratch (allocation-free rule) ----------------
__device__ __align__(16) float g_q[Bc * Tc * Hc];   // tf32-rounded, SCALE folded
__device__ __align__(16) float g_k[Bc * Tc * Hc];   // tf32-rounded
__device__ __align__(16) float g_vt[Bc * Hc * Tc];  // tf32-rounded, [b][h][t]

// ---------------- PTX helpers (sm_80+ baseline) ----------------
__device__ __forceinline__ void mma_tf32(float* d, const uint32_t* a,
                                         uint32_t b0, uint32_t b1) {
    asm volatile(
        "mma.sync.aligned.m16n8k8.row.col.f32.tf32.tf32.f32 "
        "{%0,%1,%2,%3}, {%4,%5,%6,%7}, {%8,%9}, {%0,%1,%2,%3};"
        : "+f"(d[0]), "+f"(d[1]), "+f"(d[2]), "+f"(d[3])
        : "r"(a[0]), "r"(a[1]), "r"(a[2]), "r"(a[3]), "r"(b0), "r"(b1));
}
__device__ __forceinline__ uint32_t lds32(uint32_t a) {
    uint32_t v;
    asm volatile("ld.shared.b32 %0, [%1];" : "=r"(v) : "r"(a));
    return v;
}
__device__ __forceinline__ uint32_t smem_u32(const void* p) {
    uint32_t a;
    asm("{ .reg .u64 t; cvta.to.shared.u64 t, %1; cvt.u32.u64 %0, t; }"
        : "=r"(a) : "l"(p));
    return a;
}
__device__ __forceinline__ void cpasync16(uint32_t dst, const void* src) {
    asm volatile("cp.async.ca.shared.global [%0], [%1], 16;" :: "r"(dst), "l"(src));
}
#define CP_COMMIT() asm volatile("cp.async.commit_group;" ::: "memory")
#define CP_WAIT0()  asm volatile("cp.async.wait_group 0;" ::: "memory")

__device__ __forceinline__ float to_tf32(float x) {
    float r;
    asm("cvt.rna.tf32.f32 %0, %1;" : "=f"(r) : "f"(x));
    return r;
}
__device__ __forceinline__ unsigned long long ffma2(unsigned long long a,
                                                    unsigned long long b,
                                                    unsigned long long c) {
    unsigned long long d;
    asm("fma.rn.f32x2 %0, %1, %2, %3;" : "=l"(d) : "l"(a), "l"(b), "l"(c));
    return d;
}
__device__ __forceinline__ float2 u2f(unsigned long long u) {
    float2 r;
    asm("mov.b64 {%0, %1}, %2;" : "=f"(r.x), "=f"(r.y) : "l"(u));
    return r;
}
__device__ __forceinline__ unsigned long long pk64(float lo, float hi) {
    unsigned long long r;
    asm("mov.b64 %0, {%1, %2};" : "=l"(r) : "f"(lo), "f"(hi));
    return r;
}

// ---------------- Kernel 1: QKV projection (tf32 outputs) ----------------
// 512 CTAs x 192 threads; 32 rows/CTA; thread = (matrix m, column h).
constexpr int PROJ_SMEM = (3 * Cc * Hc + 32 * Cc) * 4;  // 107,520 B
__global__ void __launch_bounds__(192)
proj_kernel(const float* __restrict__ x,
            const float* __restrict__ Wk,
            const float* __restrict__ Wq,
            const float* __restrict__ Wv) {
    extern __shared__ float ps[];
    float* sW = ps;                 // [3][120][64]
    float* xs = ps + 3 * Cc * Hc;   // [32][120]

    const int tid = threadIdx.x;
    {
        const float4* s0 = reinterpret_cast<const float4*>(Wk);
        const float4* s1 = reinterpret_cast<const float4*>(Wq);
        const float4* s2 = reinterpret_cast<const float4*>(Wv);
        float4* d0 = reinterpret_cast<float4*>(sW);
        float4* d1 = reinterpret_cast<float4*>(sW + Cc * Hc);
        float4* d2 = reinterpret_cast<float4*>(sW + 2 * Cc * Hc);
#pragma unroll
        for (int j = tid; j < Cc * Hc / 4; j += 192) {
            d0[j] = s0[j];
            d1[j] = s1[j];
            d2[j] = s2[j];
        }
    }
    const int row0 = blockIdx.x * 32;
    {
        const float4* xg = reinterpret_cast<const float4*>(x + (long long)row0 * Cc);
        float4* xs4 = reinterpret_cast<float4*>(xs);
#pragma unroll
        for (int i = 0; i < 5; i++) xs4[tid + i * 192] = xg[tid + i * 192];
    }
    __syncthreads();

    const int m = tid >> 6, h = tid & 63;
    const float* wcol = sW + m * Cc * Hc + h;

    unsigned long long acc[32];
#pragma unroll
    for (int r = 0; r < 32; r++) acc[r] = 0ull;

#pragma unroll 1
    for (int c8 = 0; c8 < 15; c8++) {
        float wv[8];
#pragma unroll
        for (int i = 0; i < 8; i++) wv[i] = wcol[(c8 * 8 + i) * Hc];
        const unsigned long long w0 = pk64(wv[0], wv[1]);
        const unsigned long long w1 = pk64(wv[2], wv[3]);
        const unsigned long long w2 = pk64(wv[4], wv[5]);
        const unsigned long long w3 = pk64(wv[6], wv[7]);
#pragma unroll
        for (int r = 0; r < 32; r++) {
            const ulonglong2 x01 = *reinterpret_cast<const ulonglong2*>(&xs[r * Cc + c8 * 8]);
            const ulonglong2 x23 = *reinterpret_cast<const ulonglong2*>(&xs[r * Cc + c8 * 8 + 4]);
            acc[r] = ffma2(x01.x, w0, acc[r]);
            acc[r] = ffma2(x01.y, w1, acc[r]);
            acc[r] = ffma2(x23.x, w2, acc[r]);
            acc[r] = ffma2(x23.y, w3, acc[r]);
        }
    }

    if (m == 2) {
        // V: thread h already holds v[h][t0..t0+31] — contiguous STG.128 stores
        const int b = row0 >> 12, t0 = row0 & 4095;
        float4* vp = reinterpret_cast<float4*>(g_vt + ((long long)(b * Hc + h)) * Tc + t0);
#pragma unroll
        for (int i = 0; i < 8; i++) {
            const float2 f0 = u2f(acc[4 * i]);
            const float2 f1 = u2f(acc[4 * i + 1]);
            const float2 f2 = u2f(acc[4 * i + 2]);
            const float2 f3 = u2f(acc[4 * i + 3]);
            float4 t;
            t.x = to_tf32(f0.x + f0.y);
            t.y = to_tf32(f1.x + f1.y);
            t.z = to_tf32(f2.x + f2.y);
            t.w = to_tf32(f3.x + f3.y);
            vp[i] = t;
        }
    } else if (m == 1) {
        // Q (with scale)
#pragma unroll
        for (int r = 0; r < 32; r++) {
            const float2 f = u2f(acc[r]);
            g_q[(row0 + r) * Hc + h] = to_tf32((f.x + f.y) * SCALE);
        }
    } else {
        // K
#pragma unroll
        for (int r = 0; r < 32; r++) {
            const float2 f = u2f(acc[r]);
            g_k[(row0 + r) * Hc + h] = to_tf32(f.x + f.y);
        }
    }
}

// ---------------- Kernel 2: tf32 HMMA flash attention ----------------
// 128 CTAs x 256 thr; 16 q/warp; 64 key tiles of 64; per 8-key n-tile:
// QK (8 k8 MMAs, 2 accum chains) -> exp -> quad-shuffle to P A-frag -> PV
// (8 independent jd chains). Pipelined: QK(j+1) issued before exp(j).
__global__ void __launch_bounds__(256, 1)
attn_kernel(float* __restrict__ out) {
    extern __shared__ char dsm[];  // 2 x STAGE

    const int tid = threadIdx.x;
    const int w = tid >> 5;
    const int lane = tid & 31;
    const int g = lane >> 2;
    const int tig = lane & 3;
    const int b = blockIdx.y;
    const long long qrow = (long long)b * Tc + blockIdx.x * 128 + 16 * w + g;

    // ---- Q fragments (tf32 values stored as f32 bits) ----
    uint32_t qf[8][4];
#pragma unroll
    for (int s = 0; s < 8; s++) {
        const float* q0 = g_q + qrow * Hc;
        const float* q1 = g_q + (qrow + 8) * Hc;
        qf[s][0] = __float_as_uint(q0[8 * s + tig]);
        qf[s][1] = __float_as_uint(q1[8 * s + tig]);
        qf[s][2] = __float_as_uint(q0[8 * s + tig + 4]);
        qf[s][3] = __float_as_uint(q1[8 * s + tig + 4]);
    }

    float O[8][4];
#pragma unroll
    for (int j = 0; j < 8; j++)
#pragma unroll
        for (int i = 0; i < 4; i++) O[j][i] = 0.f;
    float rl = 0.f, rh = 0.f;

    const uint32_t sb = smem_u32(dsm);
    const uint32_t fragoff = (uint32_t)(g * RSTRIDE + tig * 4);

    auto prefetch = [&](int kt, int p) {
        const uint32_t bb = sb + p * STAGE;
        const long long kb = (long long)b * Tc + kt * KTILE;          // K row base
        const float* vbase = g_vt + (long long)b * Hc * Tc + kt * KTILE;
#pragma unroll
        for (int it = 0; it < 4; it++) {
            const int c = tid + it * 256;  // 0..1023
            const int row = c >> 4, col = c & 15;
            const uint32_t doff = (uint32_t)(row * RSTRIDE + col * 16);
            cpasync16(bb + doff, g_k + (kb + row) * Hc + col * 4);
            cpasync16(bb + VOFF + doff, vbase + (long long)row * Tc + col * 4);
        }
    };

    prefetch(0, 0);
    CP_COMMIT();

    float S[2][4];  // ping-pong S fragments

    for (int kt = 0; kt < NKT; kt++) {
        CP_WAIT0();
        __syncthreads();
        if (kt + 1 < NKT) {
            prefetch(kt + 1, (kt + 1) & 1);
            CP_COMMIT();
        }

        const uint32_t bb = sb + (kt & 1) * STAGE;
        const uint32_t aK = bb + fragoff;         // + j*8*RSTRIDE + s*32 (+16 for b1)
        const uint32_t aV = bb + VOFF + fragoff;  // + jd*8*RSTRIDE + s*32

        // QK for one 8-key n-tile (2 accumulation chains of depth 4)
        auto qk_ntile = [&](int j, int p) {
            float Sa[4] = {0.f, 0.f, 0.f, 0.f};
            float Sb[4] = {0.f, 0.f, 0.f, 0.f};
            const uint32_t base = aK + (uint32_t)j * (8 * RSTRIDE);
#pragma unroll
            for (int s = 0; s < 4; s++) {
                uint32_t b0 = lds32(base + (2 * s) * 32);
                uint32_t b1 = lds32(base + (2 * s) * 32 + 16);
                mma_tf32(Sa, qf[2 * s], b0, b1);
                uint32_t c0 = lds32(base + (2 * s + 1) * 32);
                uint32_t c1 = lds32(base + (2 * s + 1) * 32 + 16);
                mma_tf32(Sb, qf[2 * s + 1], c0, c1);
            }
#pragma unroll
            for (int i = 0; i < 4; i++) S[p][i] = Sa[i] + Sb[i];
        };

        qk_ntile(0, 0);

#pragma unroll
        for (int j = 0; j < 8; j++) {
            if (j < 7) qk_ntile(j + 1, (j + 1) & 1);

            const float* Sc = S[j & 1];
            const float e0 = __expf(Sc[0]), e1 = __expf(Sc[1]);
            const float e2 = __expf(Sc[2]), e3 = __expf(Sc[3]);
            rl += e0 + e1;
            rh += e2 + e3;

            // quad shuffle: C-frag cols {2tig,2tig+1} -> A-frag cols {tig,tig+4}
            const int basel = lane & ~3;
            const int hsel = tig >> 1;
            const bool odd = tig & 1;
            const float u0 = __shfl_sync(0xffffffffu, e0, basel + hsel);
            const float u1 = __shfl_sync(0xffffffffu, e1, basel + hsel);
            const float u2 = __shfl_sync(0xffffffffu, e0, basel + hsel + 2);
            const float u3 = __shfl_sync(0xffffffffu, e1, basel + hsel + 2);
            const float u4 = __shfl_sync(0xffffffffu, e2, basel + hsel);
            const float u5 = __shfl_sync(0xffffffffu, e3, basel + hsel);
            const float u6 = __shfl_sync(0xffffffffu, e2, basel + hsel + 2);
            const float u7 = __shfl_sync(0xffffffffu, e3, basel + hsel + 2);
            uint32_t pf[4];
            pf[0] = __float_as_uint(to_tf32(odd ? u1 : u0));
            pf[1] = __float_as_uint(to_tf32(odd ? u5 : u4));
            pf[2] = __float_as_uint(to_tf32(odd ? u3 : u2));
            pf[3] = __float_as_uint(to_tf32(odd ? u7 : u6));

            // PV: kstep j, 8 independent jd chains
            const uint32_t vbase = aV + (uint32_t)j * 32;
#pragma unroll
            for (int jd = 0; jd < 8; jd++) {
                const uint32_t va = vbase + (uint32_t)jd * (8 * RSTRIDE);
                const uint32_t b0 = lds32(va);
                const uint32_t b1 = lds32(va + 16);
                mma_tf32(O[jd], pf, b0, b1);
            }
        }
    }

    // ---- row sums, normalize, store ----
    rl += __shfl_xor_sync(0xffffffffu, rl, 1);
    rl += __shfl_xor_sync(0xffffffffu, rl, 2);
    rh += __shfl_xor_sync(0xffffffffu, rh, 1);
    rh += __shfl_xor_sync(0xffffffffu, rh, 2);
    const float il = 1.0f / rl;
    const float ih = 1.0f / rh;

#pragma unroll
    for (int j = 0; j < 8; j++) {
        const int d0 = 8 * j + 2 * tig;
        float2 v0 = make_float2(O[j][0] * il, O[j][1] * il);
        *(float2*)&out[qrow * Hc + d0] = v0;
        float2 v1 = make_float2(O[j][2] * ih, O[j][3] * ih);
        *(float2*)&out[(qrow + 8) * Hc + d0] = v1;
    }
}

extern "C" void kernel_launch(void* const* d_in, const int* in_sizes, int n_in,
                              void* d_out, int out_size) {
    // x is the unique large tensor; weights keep relative order Wk, Wq, Wv.
    const float* x = nullptr;
    const float* w[3] = {nullptr, nullptr, nullptr};
    int wn = 0;
    for (int i = 0; i < n_in; i++) {
        if (in_sizes[i] == Bc * Tc * Cc) x = (const float*)d_in[i];
        else if (wn < 3) w[wn++] = (const float*)d_in[i];
    }

    static bool configured = false;
    if (!configured) {
        cudaFuncSetAttribute(proj_kernel, cudaFuncAttributeMaxDynamicSharedMemorySize,
                             PROJ_SMEM);
        cudaFuncSetAttribute(attn_kernel, cudaFuncAttributeMaxDynamicSharedMemorySize,
                             2 * STAGE);
        configured = true;
    }

    proj_kernel<<<512, 192, PROJ_SMEM>>>(x, w[0], w[1], w[2]);

    dim3 grid(Tc / 128, Bc);
    attn_kernel<<<grid, 256, 2 * STAGE>>>((float*)d_out);
}

// round 10
// speedup vs baseline: 1.4423x; 1.1457x over previous
#include <cuda_runtime.h>
#include <cuda_bf16.h>
#include <cstdint>

// ---------------- problem constants ----------------
constexpr int Bc = 4, Tc = 4096, Cc = 120, Hc = 64;
constexpr float SCALE = 0.09128709291752768f;  // 1/sqrt(C)
constexpr int KTILE = 64;
constexpr int HKT = 32;           // key tiles per half (Tc/KTILE/2)
constexpr int RSTRIDE = 272;      // smem row stride bytes (68 f32, conflict-free)
constexpr int VOFF = 64 * RSTRIDE;        // V region offset in stage
constexpr int STAGE = 2 * 64 * RSTRIDE;   // 34816 bytes per stage (K + V)

// ---------------- device scratch (allocation-free rule) ----------------
__device__ __align__(16) float g_q[Bc * Tc * Hc];   // tf32-rounded, SCALE folded
__device__ __align__(16) float g_k[Bc * Tc * Hc];   // tf32-rounded
__device__ __align__(16) float g_vt[Bc * Hc * Tc];  // tf32-rounded, [b][h][t]
__device__ __align__(16) float g_acc[2][Bc * Tc * Hc];  // partial O per key-half
__device__ __align__(16) float g_rs[2][Bc * Tc];        // partial rowsums

// ---------------- PTX helpers (sm_80+ baseline) ----------------
__device__ __forceinline__ void mma_tf32(float* d, const uint32_t* a,
                                         uint32_t b0, uint32_t b1) {
    asm volatile(
        "mma.sync.aligned.m16n8k8.row.col.f32.tf32.tf32.f32 "
        "{%0,%1,%2,%3}, {%4,%5,%6,%7}, {%8,%9}, {%0,%1,%2,%3};"
        : "+f"(d[0]), "+f"(d[1]), "+f"(d[2]), "+f"(d[3])
        : "r"(a[0]), "r"(a[1]), "r"(a[2]), "r"(a[3]), "r"(b0), "r"(b1));
}
__device__ __forceinline__ uint32_t lds32(uint32_t a) {
    uint32_t v;
    asm volatile("ld.shared.b32 %0, [%1];" : "=r"(v) : "r"(a));
    return v;
}
__device__ __forceinline__ uint32_t smem_u32(const void* p) {
    uint32_t a;
    asm("{ .reg .u64 t; cvta.to.shared.u64 t, %1; cvt.u32.u64 %0, t; }"
        : "=r"(a) : "l"(p));
    return a;
}
__device__ __forceinline__ void cpasync16(uint32_t dst, const void* src) {
    asm volatile("cp.async.ca.shared.global [%0], [%1], 16;" :: "r"(dst), "l"(src));
}
#define CP_COMMIT() asm volatile("cp.async.commit_group;" ::: "memory")
#define CP_WAIT0()  asm volatile("cp.async.wait_group 0;" ::: "memory")

__device__ __forceinline__ float to_tf32(float x) {
    float r;
    asm("cvt.rna.tf32.f32 %0, %1;" : "=f"(r) : "f"(x));
    return r;
}
__device__ __forceinline__ unsigned long long ffma2(unsigned long long a,
                                                    unsigned long long b,
                                                    unsigned long long c) {
    unsigned long long d;
    asm("fma.rn.f32x2 %0, %1, %2, %3;" : "=l"(d) : "l"(a), "l"(b), "l"(c));
    return d;
}
__device__ __forceinline__ float2 u2f(unsigned long long u) {
    float2 r;
    asm("mov.b64 {%0, %1}, %2;" : "=f"(r.x), "=f"(r.y) : "l"(u));
    return r;
}
__device__ __forceinline__ unsigned long long pk64(float lo, float hi) {
    unsigned long long r;
    asm("mov.b64 %0, {%1, %2};" : "=l"(r) : "f"(lo), "f"(hi));
    return r;
}

// ---------------- Kernel 1: QKV projection (tf32 outputs) ----------------
constexpr int PROJ_SMEM = (3 * Cc * Hc + 32 * Cc) * 4;  // 107,520 B
__global__ void __launch_bounds__(192)
proj_kernel(const float* __restrict__ x,
            const float* __restrict__ Wk,
            const float* __restrict__ Wq,
            const float* __restrict__ Wv) {
    extern __shared__ float ps[];
    float* sW = ps;                 // [3][120][64]
    float* xs = ps + 3 * Cc * Hc;   // [32][120]

    const int tid = threadIdx.x;
    {
        const float4* s0 = reinterpret_cast<const float4*>(Wk);
        const float4* s1 = reinterpret_cast<const float4*>(Wq);
        const float4* s2 = reinterpret_cast<const float4*>(Wv);
        float4* d0 = reinterpret_cast<float4*>(sW);
        float4* d1 = reinterpret_cast<float4*>(sW + Cc * Hc);
        float4* d2 = reinterpret_cast<float4*>(sW + 2 * Cc * Hc);
#pragma unroll
        for (int j = tid; j < Cc * Hc / 4; j += 192) {
            d0[j] = s0[j];
            d1[j] = s1[j];
            d2[j] = s2[j];
        }
    }
    const int row0 = blockIdx.x * 32;
    {
        const float4* xg = reinterpret_cast<const float4*>(x + (long long)row0 * Cc);
        float4* xs4 = reinterpret_cast<float4*>(xs);
#pragma unroll
        for (int i = 0; i < 5; i++) xs4[tid + i * 192] = xg[tid + i * 192];
    }
    __syncthreads();

    const int m = tid >> 6, h = tid & 63;
    const float* wcol = sW + m * Cc * Hc + h;

    unsigned long long acc[32];
#pragma unroll
    for (int r = 0; r < 32; r++) acc[r] = 0ull;

#pragma unroll 1
    for (int c8 = 0; c8 < 15; c8++) {
        float wv[8];
#pragma unroll
        for (int i = 0; i < 8; i++) wv[i] = wcol[(c8 * 8 + i) * Hc];
        const unsigned long long w0 = pk64(wv[0], wv[1]);
        const unsigned long long w1 = pk64(wv[2], wv[3]);
        const unsigned long long w2 = pk64(wv[4], wv[5]);
        const unsigned long long w3 = pk64(wv[6], wv[7]);
#pragma unroll
        for (int r = 0; r < 32; r++) {
            const ulonglong2 x01 = *reinterpret_cast<const ulonglong2*>(&xs[r * Cc + c8 * 8]);
            const ulonglong2 x23 = *reinterpret_cast<const ulonglong2*>(&xs[r * Cc + c8 * 8 + 4]);
            acc[r] = ffma2(x01.x, w0, acc[r]);
            acc[r] = ffma2(x01.y, w1, acc[r]);
            acc[r] = ffma2(x23.x, w2, acc[r]);
            acc[r] = ffma2(x23.y, w3, acc[r]);
        }
    }

    if (m == 2) {
        // V: thread h holds v[h][t0..t0+31] — contiguous STG.128 stores
        const int b = row0 >> 12, t0 = row0 & 4095;
        float4* vp = reinterpret_cast<float4*>(g_vt + ((long long)(b * Hc + h)) * Tc + t0);
#pragma unroll
        for (int i = 0; i < 8; i++) {
            const float2 f0 = u2f(acc[4 * i]);
            const float2 f1 = u2f(acc[4 * i + 1]);
            const float2 f2 = u2f(acc[4 * i + 2]);
            const float2 f3 = u2f(acc[4 * i + 3]);
            float4 t;
            t.x = to_tf32(f0.x + f0.y);
            t.y = to_tf32(f1.x + f1.y);
            t.z = to_tf32(f2.x + f2.y);
            t.w = to_tf32(f3.x + f3.y);
            vp[i] = t;
        }
    } else if (m == 1) {
#pragma unroll
        for (int r = 0; r < 32; r++) {
            const float2 f = u2f(acc[r]);
            g_q[(row0 + r) * Hc + h] = to_tf32((f.x + f.y) * SCALE);
        }
    } else {
#pragma unroll
        for (int r = 0; r < 32; r++) {
            const float2 f = u2f(acc[r]);
            g_k[(row0 + r) * Hc + h] = to_tf32(f.x + f.y);
        }
    }
}

// ---------------- Kernel 2: tf32 flash attention, 32 q/warp, key-split ----------------
// grid (16, 4, 2): qt, batch, key-half. 256 thr, 8 warps, 32 q/warp (2 m16
// chunks sharing each B-fragment -> smem read volume halved per unit work).
__global__ void __launch_bounds__(256, 1)
attn_kernel() {
    extern __shared__ char dsm[];  // 2 x STAGE

    const int tid = threadIdx.x;
    const int w = tid >> 5;
    const int lane = tid & 31;
    const int g = lane >> 2;
    const int tig = lane & 3;
    const int b = blockIdx.y;
    const int half = blockIdx.z;
    const int qbase = blockIdx.x * 256 + w * 32;           // within batch
    const long long qrow = (long long)b * Tc + qbase + g;  // chunk0 row (g)

    // ---- Q fragments: 2 m-chunks (rows g,g+8 and g+16,g+24) ----
    uint32_t qf0[8][4], qf1[8][4];
#pragma unroll
    for (int s = 0; s < 8; s++) {
        const float* q0 = g_q + qrow * Hc;
        const float* q1 = g_q + (qrow + 8) * Hc;
        const float* q2 = g_q + (qrow + 16) * Hc;
        const float* q3 = g_q + (qrow + 24) * Hc;
        qf0[s][0] = __float_as_uint(q0[8 * s + tig]);
        qf0[s][1] = __float_as_uint(q1[8 * s + tig]);
        qf0[s][2] = __float_as_uint(q0[8 * s + tig + 4]);
        qf0[s][3] = __float_as_uint(q1[8 * s + tig + 4]);
        qf1[s][0] = __float_as_uint(q2[8 * s + tig]);
        qf1[s][1] = __float_as_uint(q3[8 * s + tig]);
        qf1[s][2] = __float_as_uint(q2[8 * s + tig + 4]);
        qf1[s][3] = __float_as_uint(q3[8 * s + tig + 4]);
    }

    float O0[8][4], O1[8][4];
#pragma unroll
    for (int j = 0; j < 8; j++)
#pragma unroll
        for (int i = 0; i < 4; i++) { O0[j][i] = 0.f; O1[j][i] = 0.f; }
    float rl0 = 0.f, rh0 = 0.f, rl1 = 0.f, rh1 = 0.f;

    const uint32_t sb = smem_u32(dsm);
    const uint32_t fragoff = (uint32_t)(g * RSTRIDE + tig * 4);

    auto prefetch = [&](int kt, int p) {
        const uint32_t bb = sb + p * STAGE;
        const int ktg = half * HKT + kt;
        const long long kb = (long long)b * Tc + ktg * KTILE;
        const float* vbase = g_vt + (long long)b * Hc * Tc + ktg * KTILE;
#pragma unroll
        for (int it = 0; it < 4; it++) {
            const int c = tid + it * 256;  // 0..1023
            const int row = c >> 4, col = c & 15;
            const uint32_t doff = (uint32_t)(row * RSTRIDE + col * 16);
            cpasync16(bb + doff, g_k + (kb + row) * Hc + col * 4);
            cpasync16(bb + VOFF + doff, vbase + (long long)row * Tc + col * 4);
        }
    };

    prefetch(0, 0);
    CP_COMMIT();

    for (int kt = 0; kt < HKT; kt++) {
        CP_WAIT0();
        __syncthreads();
        if (kt + 1 < HKT) {
            prefetch(kt + 1, (kt + 1) & 1);
            CP_COMMIT();
        }

        const uint32_t bb = sb + (kt & 1) * STAGE;
        const uint32_t aK = bb + fragoff;
        const uint32_t aV = bb + VOFF + fragoff;

#pragma unroll
        for (int j = 0; j < 8; j++) {  // 8-key n-tiles
            float S0[4] = {0.f, 0.f, 0.f, 0.f};
            float S1[4] = {0.f, 0.f, 0.f, 0.f};
            const uint32_t base = aK + (uint32_t)j * (8 * RSTRIDE);
#pragma unroll
            for (int s = 0; s < 8; s++) {
                const uint32_t b0 = lds32(base + s * 32);
                const uint32_t b1 = lds32(base + s * 32 + 16);
                mma_tf32(S0, qf0[s], b0, b1);  // B-frag reused by both chunks
                mma_tf32(S1, qf1[s], b0, b1);
            }

            // ---- exp + quad-shuffle to A-frags (both chunks) ----
            const int basel = lane & ~3;
            const int hsel = tig >> 1;
            const bool odd = tig & 1;
            uint32_t pf0[4], pf1[4];
            {
                const float e0 = __expf(S0[0]), e1 = __expf(S0[1]);
                const float e2 = __expf(S0[2]), e3 = __expf(S0[3]);
                rl0 += e0 + e1;
                rh0 += e2 + e3;
                const float u0 = __shfl_sync(0xffffffffu, e0, basel + hsel);
                const float u1 = __shfl_sync(0xffffffffu, e1, basel + hsel);
                const float u2 = __shfl_sync(0xffffffffu, e0, basel + hsel + 2);
                const float u3 = __shfl_sync(0xffffffffu, e1, basel + hsel + 2);
                const float u4 = __shfl_sync(0xffffffffu, e2, basel + hsel);
                const float u5 = __shfl_sync(0xffffffffu, e3, basel + hsel);
                const float u6 = __shfl_sync(0xffffffffu, e2, basel + hsel + 2);
                const float u7 = __shfl_sync(0xffffffffu, e3, basel + hsel + 2);
                pf0[0] = __float_as_uint(to_tf32(odd ? u1 : u0));
                pf0[1] = __float_as_uint(to_tf32(odd ? u5 : u4));
                pf0[2] = __float_as_uint(to_tf32(odd ? u3 : u2));
                pf0[3] = __float_as_uint(to_tf32(odd ? u7 : u6));
            }
            {
                const float e0 = __expf(S1[0]), e1 = __expf(S1[1]);
                const float e2 = __expf(S1[2]), e3 = __expf(S1[3]);
                rl1 += e0 + e1;
                rh1 += e2 + e3;
                const float u0 = __shfl_sync(0xffffffffu, e0, basel + hsel);
                const float u1 = __shfl_sync(0xffffffffu, e1, basel + hsel);
                const float u2 = __shfl_sync(0xffffffffu, e0, basel + hsel + 2);
                const float u3 = __shfl_sync(0xffffffffu, e1, basel + hsel + 2);
                const float u4 = __shfl_sync(0xffffffffu, e2, basel + hsel);
                const float u5 = __shfl_sync(0xffffffffu, e3, basel + hsel);
                const float u6 = __shfl_sync(0xffffffffu, e2, basel + hsel + 2);
                const float u7 = __shfl_sync(0xffffffffu, e3, basel + hsel + 2);
                pf1[0] = __float_as_uint(to_tf32(odd ? u1 : u0));
                pf1[1] = __float_as_uint(to_tf32(odd ? u5 : u4));
                pf1[2] = __float_as_uint(to_tf32(odd ? u3 : u2));
                pf1[3] = __float_as_uint(to_tf32(odd ? u7 : u6));
            }

            // ---- PV: kstep j; V B-frags shared by both chunks ----
            const uint32_t vbase = aV + (uint32_t)j * 32;
#pragma unroll
            for (int jd = 0; jd < 8; jd++) {
                const uint32_t va = vbase + (uint32_t)jd * (8 * RSTRIDE);
                const uint32_t b0 = lds32(va);
                const uint32_t b1 = lds32(va + 16);
                mma_tf32(O0[jd], pf0, b0, b1);
                mma_tf32(O1[jd], pf1, b0, b1);
            }
        }
    }

    // ---- reduce rowsums over tig; write partial O + rowsums ----
    rl0 += __shfl_xor_sync(0xffffffffu, rl0, 1);
    rl0 += __shfl_xor_sync(0xffffffffu, rl0, 2);
    rh0 += __shfl_xor_sync(0xffffffffu, rh0, 1);
    rh0 += __shfl_xor_sync(0xffffffffu, rh0, 2);
    rl1 += __shfl_xor_sync(0xffffffffu, rl1, 1);
    rl1 += __shfl_xor_sync(0xffffffffu, rl1, 2);
    rh1 += __shfl_xor_sync(0xffffffffu, rh1, 1);
    rh1 += __shfl_xor_sync(0xffffffffu, rh1, 2);

    float* acc = g_acc[half];
    if (tig == 0) {
        float* rs = g_rs[half] + (long long)b * Tc + qbase + g;
        rs[0] = rl0;
        rs[8] = rh0;
        rs[16] = rl1;
        rs[24] = rh1;
    }
#pragma unroll
    for (int j = 0; j < 8; j++) {
        const int d0 = 8 * j + 2 * tig;
        *(float2*)&acc[qrow * Hc + d0] = make_float2(O0[j][0], O0[j][1]);
        *(float2*)&acc[(qrow + 8) * Hc + d0] = make_float2(O0[j][2], O0[j][3]);
        *(float2*)&acc[(qrow + 16) * Hc + d0] = make_float2(O1[j][0], O1[j][1]);
        *(float2*)&acc[(qrow + 24) * Hc + d0] = make_float2(O1[j][2], O1[j][3]);
    }
}

// ---------------- Kernel 3: combine key-halves + normalize ----------------
__global__ void __launch_bounds__(256)
combine_kernel(float* __restrict__ out) {
    const int idx = blockIdx.x * 256 + threadIdx.x;  // 0 .. B*T*16-1
    const int row = idx >> 4;
    const float4 a = reinterpret_cast<const float4*>(g_acc[0])[idx];
    const float4 d = reinterpret_cast<const float4*>(g_acc[1])[idx];
    const float inv = 1.0f / (g_rs[0][row] + g_rs[1][row]);
    float4 o;
    o.x = (a.x + d.x) * inv;
    o.y = (a.y + d.y) * inv;
    o.z = (a.z + d.z) * inv;
    o.w = (a.w + d.w) * inv;
    reinterpret_cast<float4*>(out)[idx] = o;
}

extern "C" void kernel_launch(void* const* d_in, const int* in_sizes, int n_in,
                              void* d_out, int out_size) {
    // x is the unique large tensor; weights keep relative order Wk, Wq, Wv.
    const float* x = nullptr;
    const float* w[3] = {nullptr, nullptr, nullptr};
    int wn = 0;
    for (int i = 0; i < n_in; i++) {
        if (in_sizes[i] == Bc * Tc * Cc) x = (const float*)d_in[i];
        else if (wn < 3) w[wn++] = (const float*)d_in[i];
    }

    static bool configured = false;
    if (!configured) {
        cudaFuncSetAttribute(proj_kernel, cudaFuncAttributeMaxDynamicSharedMemorySize,
                             PROJ_SMEM);
        cudaFuncSetAttribute(attn_kernel, cudaFuncAttributeMaxDynamicSharedMemorySize,
                             2 * STAGE);
        configured = true;
    }

    proj_kernel<<<512, 192, PROJ_SMEM>>>(x, w[0], w[1], w[2]);

    dim3 grid(Tc / 256, Bc, 2);
    attn_kernel<<<grid, 256, 2 * STAGE>>>();

    combine_kernel<<<Bc * Tc * 16 / 256, 256>>>((float*)d_out);
}

// round 11
// speedup vs baseline: 1.5529x; 1.0766x over previous
#include <cuda_runtime.h>
#include <cuda_bf16.h>
#include <cstdint>

// ---------------- problem constants ----------------
constexpr int Bc = 4, Tc = 4096, Cc = 120, Hc = 64;
constexpr float SCALE = 0.09128709291752768f;  // 1/sqrt(C)
constexpr int KTILE = 64;
constexpr int HKT = 32;           // key tiles per half (Tc/KTILE/2)
constexpr int RSTRIDE = 288;      // smem row stride bytes (72 words, 72%32=8 -> LDS.64 conflict-free)
constexpr int VOFF = 64 * RSTRIDE;        // V region offset in stage (18432)
constexpr int STAGE = 2 * 64 * RSTRIDE;   // 36864 bytes per stage (K + V)

// ---------------- device scratch (allocation-free rule) ----------------
__device__ __align__(16) float g_q[Bc * Tc * Hc];   // tf32-rounded, SCALE folded
__device__ __align__(16) float g_k[Bc * Tc * Hc];   // tf32-rounded
__device__ __align__(16) float g_vt[Bc * Hc * Tc];  // tf32-rounded, [b][h][t]
__device__ __align__(16) float g_acc[2][Bc * Tc * Hc];  // partial O per key-half
__device__ __align__(16) float g_rs[2][Bc * Tc];        // partial rowsums

// ---------------- PTX helpers (sm_80+ baseline) ----------------
__device__ __forceinline__ void mma_tf32(float* d, const uint32_t* a,
                                         uint32_t b0, uint32_t b1) {
    asm volatile(
        "mma.sync.aligned.m16n8k8.row.col.f32.tf32.tf32.f32 "
        "{%0,%1,%2,%3}, {%4,%5,%6,%7}, {%8,%9}, {%0,%1,%2,%3};"
        : "+f"(d[0]), "+f"(d[1]), "+f"(d[2]), "+f"(d[3])
        : "r"(a[0]), "r"(a[1]), "r"(a[2]), "r"(a[3]), "r"(b0), "r"(b1));
}
__device__ __forceinline__ void lds64(uint32_t& r0, uint32_t& r1, uint32_t a) {
    asm volatile("ld.shared.v2.b32 {%0,%1}, [%2];" : "=r"(r0), "=r"(r1) : "r"(a));
}
__device__ __forceinline__ uint32_t smem_u32(const void* p) {
    uint32_t a;
    asm("{ .reg .u64 t; cvta.to.shared.u64 t, %1; cvt.u32.u64 %0, t; }"
        : "=r"(a) : "l"(p));
    return a;
}
__device__ __forceinline__ void cpasync16(uint32_t dst, const void* src) {
    asm volatile("cp.async.ca.shared.global [%0], [%1], 16;" :: "r"(dst), "l"(src));
}
#define CP_COMMIT() asm volatile("cp.async.commit_group;" ::: "memory")
#define CP_WAIT0()  asm volatile("cp.async.wait_group 0;" ::: "memory")

__device__ __forceinline__ float to_tf32(float x) {
    float r;
    asm("cvt.rna.tf32.f32 %0, %1;" : "=f"(r) : "f"(x));
    return r;
}
__device__ __forceinline__ unsigned long long ffma2(unsigned long long a,
                                                    unsigned long long b,
                                                    unsigned long long c) {
    unsigned long long d;
    asm("fma.rn.f32x2 %0, %1, %2, %3;" : "=l"(d) : "l"(a), "l"(b), "l"(c));
    return d;
}
__device__ __forceinline__ float2 u2f(unsigned long long u) {
    float2 r;
    asm("mov.b64 {%0, %1}, %2;" : "=f"(r.x), "=f"(r.y) : "l"(u));
    return r;
}
__device__ __forceinline__ unsigned long long pk64(float lo, float hi) {
    unsigned long long r;
    asm("mov.b64 %0, {%1, %2};" : "=l"(r) : "f"(lo), "f"(hi));
    return r;
}

// ---------------- Kernel 1: QKV projection (tf32 outputs) ----------------
constexpr int PROJ_SMEM = (3 * Cc * Hc + 32 * Cc) * 4;  // 107,520 B
__global__ void __launch_bounds__(192)
proj_kernel(const float* __restrict__ x,
            const float* __restrict__ Wk,
            const float* __restrict__ Wq,
            const float* __restrict__ Wv) {
    extern __shared__ float ps[];
    float* sW = ps;                 // [3][120][64]
    float* xs = ps + 3 * Cc * Hc;   // [32][120]

    const int tid = threadIdx.x;
    {
        const float4* s0 = reinterpret_cast<const float4*>(Wk);
        const float4* s1 = reinterpret_cast<const float4*>(Wq);
        const float4* s2 = reinterpret_cast<const float4*>(Wv);
        float4* d0 = reinterpret_cast<float4*>(sW);
        float4* d1 = reinterpret_cast<float4*>(sW + Cc * Hc);
        float4* d2 = reinterpret_cast<float4*>(sW + 2 * Cc * Hc);
#pragma unroll
        for (int j = tid; j < Cc * Hc / 4; j += 192) {
            d0[j] = s0[j];
            d1[j] = s1[j];
            d2[j] = s2[j];
        }
    }
    const int row0 = blockIdx.x * 32;
    {
        const float4* xg = reinterpret_cast<const float4*>(x + (long long)row0 * Cc);
        float4* xs4 = reinterpret_cast<float4*>(xs);
#pragma unroll
        for (int i = 0; i < 5; i++) xs4[tid + i * 192] = xg[tid + i * 192];
    }
    __syncthreads();

    const int m = tid >> 6, h = tid & 63;
    const float* wcol = sW + m * Cc * Hc + h;

    unsigned long long acc[32];
#pragma unroll
    for (int r = 0; r < 32; r++) acc[r] = 0ull;

#pragma unroll 1
    for (int c8 = 0; c8 < 15; c8++) {
        float wv[8];
#pragma unroll
        for (int i = 0; i < 8; i++) wv[i] = wcol[(c8 * 8 + i) * Hc];
        const unsigned long long w0 = pk64(wv[0], wv[1]);
        const unsigned long long w1 = pk64(wv[2], wv[3]);
        const unsigned long long w2 = pk64(wv[4], wv[5]);
        const unsigned long long w3 = pk64(wv[6], wv[7]);
#pragma unroll
        for (int r = 0; r < 32; r++) {
            const ulonglong2 x01 = *reinterpret_cast<const ulonglong2*>(&xs[r * Cc + c8 * 8]);
            const ulonglong2 x23 = *reinterpret_cast<const ulonglong2*>(&xs[r * Cc + c8 * 8 + 4]);
            acc[r] = ffma2(x01.x, w0, acc[r]);
            acc[r] = ffma2(x01.y, w1, acc[r]);
            acc[r] = ffma2(x23.x, w2, acc[r]);
            acc[r] = ffma2(x23.y, w3, acc[r]);
        }
    }

    if (m == 2) {
        // V: thread h holds v[h][t0..t0+31] — contiguous STG.128 stores
        const int b = row0 >> 12, t0 = row0 & 4095;
        float4* vp = reinterpret_cast<float4*>(g_vt + ((long long)(b * Hc + h)) * Tc + t0);
#pragma unroll
        for (int i = 0; i < 8; i++) {
            const float2 f0 = u2f(acc[4 * i]);
            const float2 f1 = u2f(acc[4 * i + 1]);
            const float2 f2 = u2f(acc[4 * i + 2]);
            const float2 f3 = u2f(acc[4 * i + 3]);
            float4 t;
            t.x = to_tf32(f0.x + f0.y);
            t.y = to_tf32(f1.x + f1.y);
            t.z = to_tf32(f2.x + f2.y);
            t.w = to_tf32(f3.x + f3.y);
            vp[i] = t;
        }
    } else if (m == 1) {
#pragma unroll
        for (int r = 0; r < 32; r++) {
            const float2 f = u2f(acc[r]);
            g_q[(row0 + r) * Hc + h] = to_tf32((f.x + f.y) * SCALE);
        }
    } else {
#pragma unroll
        for (int r = 0; r < 32; r++) {
            const float2 f = u2f(acc[r]);
            g_k[(row0 + r) * Hc + h] = to_tf32(f.x + f.y);
        }
    }
}

// ---------------- Kernel 2: tf32 flash attention, 32 q/warp, key-split ----------------
// Contraction-index relabeling: A-slot t <-> key/dim 2t, slot t+4 <-> 2t+1.
// QK C-fragment becomes the PV A-fragment directly (no shuffles), and every
// B-fragment pair is adjacent in smem (ld.shared.v2.b32).
__global__ void __launch_bounds__(256, 1)
attn_kernel() {
    extern __shared__ char dsm[];  // 2 x STAGE

    const int tid = threadIdx.x;
    const int w = tid >> 5;
    const int lane = tid & 31;
    const int g = lane >> 2;
    const int tig = lane & 3;
    const int b = blockIdx.y;
    const int half = blockIdx.z;
    const int qbase = blockIdx.x * 256 + w * 32;
    const long long qrow = (long long)b * Tc + qbase + g;

    // ---- Q fragments: dims {8s+2tig, 8s+2tig+1} in slots {tig, tig+4} ----
    uint32_t qf0[8][4], qf1[8][4];
#pragma unroll
    for (int s = 0; s < 8; s++) {
        const float2 a0 = *(const float2*)&g_q[qrow * Hc + 8 * s + 2 * tig];
        const float2 a1 = *(const float2*)&g_q[(qrow + 8) * Hc + 8 * s + 2 * tig];
        const float2 a2 = *(const float2*)&g_q[(qrow + 16) * Hc + 8 * s + 2 * tig];
        const float2 a3 = *(const float2*)&g_q[(qrow + 24) * Hc + 8 * s + 2 * tig];
        qf0[s][0] = __float_as_uint(a0.x);
        qf0[s][1] = __float_as_uint(a1.x);
        qf0[s][2] = __float_as_uint(a0.y);
        qf0[s][3] = __float_as_uint(a1.y);
        qf1[s][0] = __float_as_uint(a2.x);
        qf1[s][1] = __float_as_uint(a3.x);
        qf1[s][2] = __float_as_uint(a2.y);
        qf1[s][3] = __float_as_uint(a3.y);
    }

    float O0[8][4], O1[8][4];
#pragma unroll
    for (int j = 0; j < 8; j++)
#pragma unroll
        for (int i = 0; i < 4; i++) { O0[j][i] = 0.f; O1[j][i] = 0.f; }
    float rl0 = 0.f, rh0 = 0.f, rl1 = 0.f, rh1 = 0.f;

    const uint32_t sb = smem_u32(dsm);
    const uint32_t fragoff = (uint32_t)(g * RSTRIDE + tig * 8);

    auto prefetch = [&](int kt, int p) {
        const uint32_t bb = sb + p * STAGE;
        const int ktg = half * HKT + kt;
        const long long kb = (long long)b * Tc + ktg * KTILE;
        const float* vbase = g_vt + (long long)b * Hc * Tc + ktg * KTILE;
#pragma unroll
        for (int it = 0; it < 4; it++) {
            const int c = tid + it * 256;  // 0..1023
            const int row = c >> 4, col = c & 15;
            const uint32_t doff = (uint32_t)(row * RSTRIDE + col * 16);
            cpasync16(bb + doff, g_k + (kb + row) * Hc + col * 4);
            cpasync16(bb + VOFF + doff, vbase + (long long)row * Tc + col * 4);
        }
    };

    prefetch(0, 0);
    CP_COMMIT();

    for (int kt = 0; kt < HKT; kt++) {
        CP_WAIT0();
        __syncthreads();
        if (kt + 1 < HKT) {
            prefetch(kt + 1, (kt + 1) & 1);
            CP_COMMIT();
        }

        const uint32_t bb = sb + (kt & 1) * STAGE;
        const uint32_t aK = bb + fragoff;
        const uint32_t aV = bb + VOFF + fragoff;

#pragma unroll
        for (int j = 0; j < 8; j++) {  // 8-key n-tiles
            float S0[4] = {0.f, 0.f, 0.f, 0.f};
            float S1[4] = {0.f, 0.f, 0.f, 0.f};
            const uint32_t base = aK + (uint32_t)j * (8 * RSTRIDE);
#pragma unroll
            for (int s = 0; s < 8; s++) {
                uint32_t b0, b1;
                lds64(b0, b1, base + s * 32);      // dims {8s+2tig, 8s+2tig+1}
                mma_tf32(S0, qf0[s], b0, b1);      // B-frag reused by both chunks
                mma_tf32(S1, qf1[s], b0, b1);
            }

            // ---- exp; C-frag IS the A-frag under the relabeling ----
            uint32_t pf0[4], pf1[4];
            {
                const float e0 = __expf(S0[0]), e1 = __expf(S0[1]);
                const float e2 = __expf(S0[2]), e3 = __expf(S0[3]);
                rl0 += e0 + e1;
                rh0 += e2 + e3;
                pf0[0] = __float_as_uint(to_tf32(e0));
                pf0[1] = __float_as_uint(to_tf32(e2));
                pf0[2] = __float_as_uint(to_tf32(e1));
                pf0[3] = __float_as_uint(to_tf32(e3));
            }
            {
                const float e0 = __expf(S1[0]), e1 = __expf(S1[1]);
                const float e2 = __expf(S1[2]), e3 = __expf(S1[3]);
                rl1 += e0 + e1;
                rh1 += e2 + e3;
                pf1[0] = __float_as_uint(to_tf32(e0));
                pf1[1] = __float_as_uint(to_tf32(e2));
                pf1[2] = __float_as_uint(to_tf32(e1));
                pf1[3] = __float_as_uint(to_tf32(e3));
            }

            // ---- PV: B rows = keys {8j+2tig, 8j+2tig+1} (adjacent words) ----
            const uint32_t vbase = aV + (uint32_t)j * 32;
#pragma unroll
            for (int jd = 0; jd < 8; jd++) {
                uint32_t b0, b1;
                lds64(b0, b1, vbase + (uint32_t)jd * (8 * RSTRIDE));
                mma_tf32(O0[jd], pf0, b0, b1);
                mma_tf32(O1[jd], pf1, b0, b1);
            }
        }
    }

    // ---- reduce rowsums over tig; write partial O + rowsums ----
    rl0 += __shfl_xor_sync(0xffffffffu, rl0, 1);
    rl0 += __shfl_xor_sync(0xffffffffu, rl0, 2);
    rh0 += __shfl_xor_sync(0xffffffffu, rh0, 1);
    rh0 += __shfl_xor_sync(0xffffffffu, rh0, 2);
    rl1 += __shfl_xor_sync(0xffffffffu, rl1, 1);
    rl1 += __shfl_xor_sync(0xffffffffu, rl1, 2);
    rh1 += __shfl_xor_sync(0xffffffffu, rh1, 1);
    rh1 += __shfl_xor_sync(0xffffffffu, rh1, 2);

    float* acc = g_acc[half];
    if (tig == 0) {
        float* rs = g_rs[half] + (long long)b * Tc + qbase + g;
        rs[0] = rl0;
        rs[8] = rh0;
        rs[16] = rl1;
        rs[24] = rh1;
    }
#pragma unroll
    for (int j = 0; j < 8; j++) {
        const int d0 = 8 * j + 2 * tig;
        *(float2*)&acc[qrow * Hc + d0] = make_float2(O0[j][0], O0[j][1]);
        *(float2*)&acc[(qrow + 8) * Hc + d0] = make_float2(O0[j][2], O0[j][3]);
        *(float2*)&acc[(qrow + 16) * Hc + d0] = make_float2(O1[j][0], O1[j][1]);
        *(float2*)&acc[(qrow + 24) * Hc + d0] = make_float2(O1[j][2], O1[j][3]);
    }
}

// ---------------- Kernel 3: combine key-halves + normalize ----------------
__global__ void __launch_bounds__(256)
combine_kernel(float* __restrict__ out) {
    const int idx = blockIdx.x * 256 + threadIdx.x;  // 0 .. B*T*16-1
    const int row = idx >> 4;
    const float4 a = reinterpret_cast<const float4*>(g_acc[0])[idx];
    const float4 d = reinterpret_cast<const float4*>(g_acc[1])[idx];
    const float inv = 1.0f / (g_rs[0][row] + g_rs[1][row]);
    float4 o;
    o.x = (a.x + d.x) * inv;
    o.y = (a.y + d.y) * inv;
    o.z = (a.z + d.z) * inv;
    o.w = (a.w + d.w) * inv;
    reinterpret_cast<float4*>(out)[idx] = o;
}

extern "C" void kernel_launch(void* const* d_in, const int* in_sizes, int n_in,
                              void* d_out, int out_size) {
    // x is the unique large tensor; weights keep relative order Wk, Wq, Wv.
    const float* x = nullptr;
    const float* w[3] = {nullptr, nullptr, nullptr};
    int wn = 0;
    for (int i = 0; i < n_in; i++) {
        if (in_sizes[i] == Bc * Tc * Cc) x = (const float*)d_in[i];
        else if (wn < 3) w[wn++] = (const float*)d_in[i];
    }

    static bool configured = false;
    if (!configured) {
        cudaFuncSetAttribute(proj_kernel, cudaFuncAttributeMaxDynamicSharedMemorySize,
                             PROJ_SMEM);
        cudaFuncSetAttribute(attn_kernel, cudaFuncAttributeMaxDynamicSharedMemorySize,
                             2 * STAGE);
        configured = true;
    }

    proj_kernel<<<512, 192, PROJ_SMEM>>>(x, w[0], w[1], w[2]);

    dim3 grid(Tc / 256, Bc, 2);
    attn_kernel<<<grid, 256, 2 * STAGE>>>();

    combine_kernel<<<Bc * Tc * 16 / 256, 256>>>((float*)d_out);
}

// round 12
// speedup vs baseline: 1.7978x; 1.1577x over previous
#include <cuda_runtime.h>
#include <cuda_bf16.h>
#include <cstdint>

// ---------------- problem constants ----------------
constexpr int Bc = 4, Tc = 4096, Cc = 120, Hc = 64;
constexpr float SCALE = 0.09128709291752768f;  // 1/sqrt(C)
constexpr int KTILE = 64;
constexpr int HKT = 32;           // key tiles per half (Tc/KTILE/2)
constexpr int RSTRIDE = 288;      // smem row stride bytes (72 words; 72%32=8 -> LDS.64 conflict-free)
constexpr int VOFF = 64 * RSTRIDE;        // V region offset in stage
constexpr int STAGE = 2 * 64 * RSTRIDE;   // 36864 bytes per stage (K + V)

// ---------------- device scratch (allocation-free rule) ----------------
__device__ __align__(16) float g_q[Bc * Tc * Hc];   // tf32-rounded, SCALE folded
__device__ __align__(16) float g_k[Bc * Tc * Hc];   // tf32-rounded
__device__ __align__(16) float g_vt[Bc * Hc * Tc];  // tf32-rounded, [b][h][t]
__device__ __align__(16) float g_acc[2][Bc * Tc * Hc];  // partial O per key-half
__device__ __align__(16) float g_rs[2][Bc * Tc];        // partial rowsums

// ---------------- PTX helpers (sm_80+ baseline) ----------------
__device__ __forceinline__ void mma_tf32(float* d, const uint32_t* a,
                                         uint32_t b0, uint32_t b1) {
    asm volatile(
        "mma.sync.aligned.m16n8k8.row.col.f32.tf32.tf32.f32 "
        "{%0,%1,%2,%3}, {%4,%5,%6,%7}, {%8,%9}, {%0,%1,%2,%3};"
        : "+f"(d[0]), "+f"(d[1]), "+f"(d[2]), "+f"(d[3])
        : "r"(a[0]), "r"(a[1]), "r"(a[2]), "r"(a[3]), "r"(b0), "r"(b1));
}
__device__ __forceinline__ void lds64(uint32_t& r0, uint32_t& r1, uint32_t a) {
    asm volatile("ld.shared.v2.b32 {%0,%1}, [%2];" : "=r"(r0), "=r"(r1) : "r"(a));
}
__device__ __forceinline__ uint32_t smem_u32(const void* p) {
    uint32_t a;
    asm("{ .reg .u64 t; cvta.to.shared.u64 t, %1; cvt.u32.u64 %0, t; }"
        : "=r"(a) : "l"(p));
    return a;
}
__device__ __forceinline__ void cpasync16(uint32_t dst, const void* src) {
    asm volatile("cp.async.ca.shared.global [%0], [%1], 16;" :: "r"(dst), "l"(src));
}
#define CP_COMMIT() asm volatile("cp.async.commit_group;" ::: "memory")
#define CP_WAIT0()  asm volatile("cp.async.wait_group 0;" ::: "memory")

__device__ __forceinline__ float to_tf32(float x) {
    float r;
    asm("cvt.rna.tf32.f32 %0, %1;" : "=f"(r) : "f"(x));
    return r;
}

// ---------------- Kernel 1: tf32 MMA QKV projection ----------------
// 128 CTAs x 256 thr (one wave). Per CTA: 128 token rows; x tile + all 3 W
// (transposed) staged in smem tf32-rounded; warp = m16 chunk; 24 n8-tiles
// (K | Q | V) x 15 k8-steps with the relabeled fragment scheme.
constexpr int PSTR = 136;  // smem row stride in words (136 % 32 == 8)
constexpr int PROJ_SMEM = (192 * PSTR + 128 * PSTR) * 4;  // 174,080 B
__global__ void __launch_bounds__(256, 1)
proj_kernel(const float* __restrict__ x,
            const float* __restrict__ Wk,
            const float* __restrict__ Wq,
            const float* __restrict__ Wv) {
    extern __shared__ float ps[];
    float* sW = ps;                // [192][PSTR]  rows: 0-63 K, 64-127 Q, 128-191 V
    float* sx = ps + 192 * PSTR;   // [128][PSTR]

    const int tid = threadIdx.x;
    const int row0 = blockIdx.x * 128;

    // ---- W transposed into smem (tf32-rounded): sW[m*64+h][c] = W_m[c][h] ----
    {
        const float* Ws[3] = {Wk, Wq, Wv};
#pragma unroll
        for (int m = 0; m < 3; m++) {
            const float* W = Ws[m];
            for (int i = tid; i < Cc * Hc; i += 256) {
                const int c = i >> 6, h = i & 63;
                sW[(m * 64 + h) * PSTR + c] = to_tf32(W[i]);
            }
        }
    }
    // ---- x tile into smem (tf32-rounded) ----
    {
        const float4* xg = reinterpret_cast<const float4*>(x + (long long)row0 * Cc);
        for (int i = tid; i < 128 * 30; i += 256) {
            const int r = i / 30, c4 = i % 30;
            float4 v = xg[i];
            v.x = to_tf32(v.x);
            v.y = to_tf32(v.y);
            v.z = to_tf32(v.z);
            v.w = to_tf32(v.w);
            *reinterpret_cast<float4*>(&sx[r * PSTR + c4 * 4]) = v;
        }
    }
    __syncthreads();

    const int w = tid >> 5, lane = tid & 31;
    const int g = lane >> 2, tig = lane & 3;
    const int m0 = w * 16;

    float acc[24][4];
#pragma unroll
    for (int nt = 0; nt < 24; nt++)
#pragma unroll
        for (int i = 0; i < 4; i++) acc[nt][i] = 0.f;

    const uint32_t aA0 = smem_u32(sx) + (uint32_t)(((m0 + g) * PSTR + 2 * tig) * 4);
    const uint32_t aA1 = aA0 + (uint32_t)(8 * PSTR * 4);
    const uint32_t aB  = smem_u32(sW) + (uint32_t)((g * PSTR + 2 * tig) * 4);

#pragma unroll
    for (int s = 0; s < 15; s++) {
        uint32_t a0, a1, a2, a3;
        lds64(a0, a2, aA0 + (uint32_t)s * 32);   // rows m0+g:   cols 8s+2tig, +1
        lds64(a1, a3, aA1 + (uint32_t)s * 32);   // rows m0+g+8
        uint32_t af[4] = {a0, a1, a2, a3};
#pragma unroll
        for (int nt = 0; nt < 24; nt++) {
            uint32_t b0, b1;
            lds64(b0, b1, aB + (uint32_t)(nt * 8 * PSTR) * 4 + (uint32_t)s * 32);
            mma_tf32(acc[nt], af, b0, b1);
        }
    }

    // ---- epilogue: tf32-round and store K / Q(scaled) / V(transposed) ----
    const int t0 = row0 + m0 + g;
#pragma unroll
    for (int nt = 0; nt < 8; nt++) {  // K: n 0..63
        const int h = nt * 8 + 2 * tig;
        *(float2*)&g_k[(long long)t0 * Hc + h] =
            make_float2(to_tf32(acc[nt][0]), to_tf32(acc[nt][1]));
        *(float2*)&g_k[(long long)(t0 + 8) * Hc + h] =
            make_float2(to_tf32(acc[nt][2]), to_tf32(acc[nt][3]));
    }
#pragma unroll
    for (int nt = 8; nt < 16; nt++) {  // Q: n 64..127 (scale folded)
        const int h = (nt - 8) * 8 + 2 * tig;
        *(float2*)&g_q[(long long)t0 * Hc + h] =
            make_float2(to_tf32(acc[nt][0] * SCALE), to_tf32(acc[nt][1] * SCALE));
        *(float2*)&g_q[(long long)(t0 + 8) * Hc + h] =
            make_float2(to_tf32(acc[nt][2] * SCALE), to_tf32(acc[nt][3] * SCALE));
    }
    {
        const int b = row0 >> 12, tl = t0 & 4095;
#pragma unroll
        for (int nt = 16; nt < 24; nt++) {  // V: n 128..191, transposed [h][t]
            const int h = (nt - 16) * 8 + 2 * tig;
            float* v0 = g_vt + ((long long)(b * Hc + h)) * Tc + tl;
            float* v1 = g_vt + ((long long)(b * Hc + h + 1)) * Tc + tl;
            v0[0] = to_tf32(acc[nt][0]);
            v1[0] = to_tf32(acc[nt][1]);
            v0[8] = to_tf32(acc[nt][2]);
            v1[8] = to_tf32(acc[nt][3]);
        }
    }
}

// ---------------- Kernel 2: tf32 flash attention, 32 q/warp, key-split ----------------
// Contraction-index relabeling: QK C-fragment is the PV A-fragment directly
// (no shuffles); every B-fragment pair adjacent in smem (ld.shared.v2.b32).
__global__ void __launch_bounds__(256, 1)
attn_kernel() {
    extern __shared__ char dsm[];  // 2 x STAGE

    const int tid = threadIdx.x;
    const int w = tid >> 5;
    const int lane = tid & 31;
    const int g = lane >> 2;
    const int tig = lane & 3;
    const int b = blockIdx.y;
    const int half = blockIdx.z;
    const int qbase = blockIdx.x * 256 + w * 32;
    const long long qrow = (long long)b * Tc + qbase + g;

    // ---- Q fragments: dims {8s+2tig, 8s+2tig+1} in slots {tig, tig+4} ----
    uint32_t qf0[8][4], qf1[8][4];
#pragma unroll
    for (int s = 0; s < 8; s++) {
        const float2 a0 = *(const float2*)&g_q[qrow * Hc + 8 * s + 2 * tig];
        const float2 a1 = *(const float2*)&g_q[(qrow + 8) * Hc + 8 * s + 2 * tig];
        const float2 a2 = *(const float2*)&g_q[(qrow + 16) * Hc + 8 * s + 2 * tig];
        const float2 a3 = *(const float2*)&g_q[(qrow + 24) * Hc + 8 * s + 2 * tig];
        qf0[s][0] = __float_as_uint(a0.x);
        qf0[s][1] = __float_as_uint(a1.x);
        qf0[s][2] = __float_as_uint(a0.y);
        qf0[s][3] = __float_as_uint(a1.y);
        qf1[s][0] = __float_as_uint(a2.x);
        qf1[s][1] = __float_as_uint(a3.x);
        qf1[s][2] = __float_as_uint(a2.y);
        qf1[s][3] = __float_as_uint(a3.y);
    }

    float O0[8][4], O1[8][4];
#pragma unroll
    for (int j = 0; j < 8; j++)
#pragma unroll
        for (int i = 0; i < 4; i++) { O0[j][i] = 0.f; O1[j][i] = 0.f; }
    float rl0 = 0.f, rh0 = 0.f, rl1 = 0.f, rh1 = 0.f;

    const uint32_t sb = smem_u32(dsm);
    const uint32_t fragoff = (uint32_t)(g * RSTRIDE + tig * 8);

    auto prefetch = [&](int kt, int p) {
        const uint32_t bb = sb + p * STAGE;
        const int ktg = half * HKT + kt;
        const long long kb = (long long)b * Tc + ktg * KTILE;
        const float* vbase = g_vt + (long long)b * Hc * Tc + ktg * KTILE;
#pragma unroll
        for (int it = 0; it < 4; it++) {
            const int c = tid + it * 256;  // 0..1023
            const int row = c >> 4, col = c & 15;
            const uint32_t doff = (uint32_t)(row * RSTRIDE + col * 16);
            cpasync16(bb + doff, g_k + (kb + row) * Hc + col * 4);
            cpasync16(bb + VOFF + doff, vbase + (long long)row * Tc + col * 4);
        }
    };

    prefetch(0, 0);
    CP_COMMIT();

    for (int kt = 0; kt < HKT; kt++) {
        CP_WAIT0();
        __syncthreads();
        if (kt + 1 < HKT) {
            prefetch(kt + 1, (kt + 1) & 1);
            CP_COMMIT();
        }

        const uint32_t bb = sb + (kt & 1) * STAGE;
        const uint32_t aK = bb + fragoff;
        const uint32_t aV = bb + VOFF + fragoff;

#pragma unroll
        for (int j = 0; j < 8; j++) {  // 8-key n-tiles
            float S0[4] = {0.f, 0.f, 0.f, 0.f};
            float S1[4] = {0.f, 0.f, 0.f, 0.f};
            const uint32_t base = aK + (uint32_t)j * (8 * RSTRIDE);
#pragma unroll
            for (int s = 0; s < 8; s++) {
                uint32_t b0, b1;
                lds64(b0, b1, base + s * 32);
                mma_tf32(S0, qf0[s], b0, b1);
                mma_tf32(S1, qf1[s], b0, b1);
            }

            uint32_t pf0[4], pf1[4];
            {
                const float e0 = __expf(S0[0]), e1 = __expf(S0[1]);
                const float e2 = __expf(S0[2]), e3 = __expf(S0[3]);
                rl0 += e0 + e1;
                rh0 += e2 + e3;
                pf0[0] = __float_as_uint(to_tf32(e0));
                pf0[1] = __float_as_uint(to_tf32(e2));
                pf0[2] = __float_as_uint(to_tf32(e1));
                pf0[3] = __float_as_uint(to_tf32(e3));
            }
            {
                const float e0 = __expf(S1[0]), e1 = __expf(S1[1]);
                const float e2 = __expf(S1[2]), e3 = __expf(S1[3]);
                rl1 += e0 + e1;
                rh1 += e2 + e3;
                pf1[0] = __float_as_uint(to_tf32(e0));
                pf1[1] = __float_as_uint(to_tf32(e2));
                pf1[2] = __float_as_uint(to_tf32(e1));
                pf1[3] = __float_as_uint(to_tf32(e3));
            }

            const uint32_t vbase = aV + (uint32_t)j * 32;
#pragma unroll
            for (int jd = 0; jd < 8; jd++) {
                uint32_t b0, b1;
                lds64(b0, b1, vbase + (uint32_t)jd * (8 * RSTRIDE));
                mma_tf32(O0[jd], pf0, b0, b1);
                mma_tf32(O1[jd], pf1, b0, b1);
            }
        }
    }

    // ---- reduce rowsums over tig; write partial O + rowsums ----
    rl0 += __shfl_xor_sync(0xffffffffu, rl0, 1);
    rl0 += __shfl_xor_sync(0xffffffffu, rl0, 2);
    rh0 += __shfl_xor_sync(0xffffffffu, rh0, 1);
    rh0 += __shfl_xor_sync(0xffffffffu, rh0, 2);
    rl1 += __shfl_xor_sync(0xffffffffu, rl1, 1);
    rl1 += __shfl_xor_sync(0xffffffffu, rl1, 2);
    rh1 += __shfl_xor_sync(0xffffffffu, rh1, 1);
    rh1 += __shfl_xor_sync(0xffffffffu, rh1, 2);

    float* acc = g_acc[half];
    if (tig == 0) {
        float* rs = g_rs[half] + (long long)b * Tc + qbase + g;
        rs[0] = rl0;
        rs[8] = rh0;
        rs[16] = rl1;
        rs[24] = rh1;
    }
#pragma unroll
    for (int j = 0; j < 8; j++) {
        const int d0 = 8 * j + 2 * tig;
        *(float2*)&acc[qrow * Hc + d0] = make_float2(O0[j][0], O0[j][1]);
        *(float2*)&acc[(qrow + 8) * Hc + d0] = make_float2(O0[j][2], O0[j][3]);
        *(float2*)&acc[(qrow + 16) * Hc + d0] = make_float2(O1[j][0], O1[j][1]);
        *(float2*)&acc[(qrow + 24) * Hc + d0] = make_float2(O1[j][2], O1[j][3]);
    }
}

// ---------------- Kernel 3: combine key-halves + normalize ----------------
__global__ void __launch_bounds__(256)
combine_kernel(float* __restrict__ out) {
    const int idx = blockIdx.x * 256 + threadIdx.x;  // 0 .. B*T*16-1
    const int row = idx >> 4;
    const float4 a = reinterpret_cast<const float4*>(g_acc[0])[idx];
    const float4 d = reinterpret_cast<const float4*>(g_acc[1])[idx];
    const float inv = 1.0f / (g_rs[0][row] + g_rs[1][row]);
    float4 o;
    o.x = (a.x + d.x) * inv;
    o.y = (a.y + d.y) * inv;
    o.z = (a.z + d.z) * inv;
    o.w = (a.w + d.w) * inv;
    reinterpret_cast<float4*>(out)[idx] = o;
}

extern "C" void kernel_launch(void* const* d_in, const int* in_sizes, int n_in,
                              void* d_out, int out_size) {
    // x is the unique large tensor; weights keep relative order Wk, Wq, Wv.
    const float* x = nullptr;
    const float* w[3] = {nullptr, nullptr, nullptr};
    int wn = 0;
    for (int i = 0; i < n_in; i++) {
        if (in_sizes[i] == Bc * Tc * Cc) x = (const float*)d_in[i];
        else if (wn < 3) w[wn++] = (const float*)d_in[i];
    }

    static bool configured = false;
    if (!configured) {
        cudaFuncSetAttribute(proj_kernel, cudaFuncAttributeMaxDynamicSharedMemorySize,
                             PROJ_SMEM);
        cudaFuncSetAttribute(attn_kernel, cudaFuncAttributeMaxDynamicSharedMemorySize,
                             2 * STAGE);
        configured = true;
    }

    proj_kernel<<<128, 256, PROJ_SMEM>>>(x, w[0], w[1], w[2]);

    dim3 grid(Tc / 256, Bc, 2);
    attn_kernel<<<grid, 256, 2 * STAGE>>>();

    combine_kernel<<<Bc * Tc * 16 / 256, 256>>>((float*)d_out);
}